// round 4
// baseline (speedup 1.0000x reference)
#include <cuda_runtime.h>
#include <cuda_bf16.h>
#include <math.h>

// ---------------------------------------------------------------------------
// Problem constants
// ---------------------------------------------------------------------------
#define BATCH   16
#define DIM     192
#define HW      56
#define PIX     3136            // 56*56
#define NPIX    50176           // 16*3136
#define WS      7
#define SHIFTV  3
#define NWIN    49              // tokens per window
#define HEADS   6
#define HD      32
#define NW_GRID 8               // 56/7 windows per side
#define SCALE_Q 0.1767766952966369f   // 32^-0.5

// ---------------------------------------------------------------------------
// Scratch buffers (allocation-free: device globals)
// ---------------------------------------------------------------------------
__device__ float g_bufa [NPIX * DIM];      // win (LN1 out), later h2 (LN2 out)
__device__ float g_bufb [NPIX * DIM];      // attention out, later fc2 out
__device__ float g_bufc [NPIX * DIM];      // proj out
__device__ float g_x1   [NPIX * DIM];      // residual-1 (NCHW layout)
__device__ float g_big  [NPIX * 768];      // qkv (576 cols used), later fc1 out

// ---------------------------------------------------------------------------
// K1: LayerNorm1 + roll(-3,-3) + window partition.
// Block = 32 consecutive pixels (same batch: 3136 % 32 == 0).
// Phase 1: coalesced NCHW load into smem-transpose tile.
// Phase 2: per-warp LN of 4 pixels each, coalesced row-major window writes.
// Original pixel (y,x) lands at shifted position ((y-3)%56, (x-3)%56).
// ---------------------------------------------------------------------------
__global__ __launch_bounds__(256)
void ln1_win_kernel(const float* __restrict__ x,
                    const float* __restrict__ gam,
                    const float* __restrict__ bet,
                    float* __restrict__ win) {
    __shared__ float sm[32][193];
    int p0  = blockIdx.x * 32;
    int b   = p0 / PIX, yx0 = p0 % PIX;
    int tid = threadIdx.x, warp = tid >> 5, lane = tid & 31;

    const float* xb = x + (size_t)b * (DIM * PIX) + yx0;
#pragma unroll
    for (int cc = 0; cc < 24; ++cc) {
        int c = warp + cc * 8;
        sm[lane][c] = xb[(size_t)c * PIX + lane];
    }
    __syncthreads();

#pragma unroll
    for (int t = 0; t < 4; ++t) {
        int pix = warp * 4 + t;
        float v[6], s = 0.f, sq = 0.f;
#pragma unroll
        for (int j = 0; j < 6; ++j) {
            float u = sm[pix][lane + j * 32];
            v[j] = u; s += u; sq += u * u;
        }
#pragma unroll
        for (int o = 16; o; o >>= 1) {
            s  += __shfl_xor_sync(0xffffffffu, s,  o);
            sq += __shfl_xor_sync(0xffffffffu, sq, o);
        }
        float mu   = s * (1.f / DIM);
        float var  = sq * (1.f / DIM) - mu * mu;
        float rstd = rsqrtf(var + 1e-5f);

        int yx = yx0 + pix;
        int y  = yx / HW, xx = yx % HW;
        int y2 = (y  + HW - SHIFTV) % HW;           // roll -3: dest = (y-3) mod 56
        int x2 = (xx + HW - SHIFTV) % HW;
        int r  = b * PIX + ((y2 / WS) * NW_GRID + (x2 / WS)) * NWIN
               + (y2 % WS) * WS + (x2 % WS);
        float* wp = win + (size_t)r * DIM;
#pragma unroll
        for (int j = 0; j < 6; ++j) {
            int c = lane + j * 32;
            wp[c] = (v[j] - mu) * rstd * gam[c] + bet[c];
        }
    }
}

// ---------------------------------------------------------------------------
// Tiled fp32 SGEMM: C[M,N] = A[M,K] @ B[K,N] + bias, optional exact GELU.
// BM=128, BN=64, BK=16, 256 threads, 8x4 micro-tile. All dims divide evenly.
// ---------------------------------------------------------------------------
#define BM 128
#define BN 64
#define BK 16
#define AS_LD 132   // padded stride for As

template <int GELU>
__global__ __launch_bounds__(256)
void sgemm_kernel(const float* __restrict__ A, const float* __restrict__ B,
                  const float* __restrict__ bias, float* __restrict__ C,
                  int M, int N, int K) {
    __shared__ float As[BK * AS_LD];   // [k][m], padded
    __shared__ float Bs[BK * BN];      // [k][n]

    int tid = threadIdx.x;
    int tx = tid & 15, ty = tid >> 4;          // 16 x 16
    int m0 = blockIdx.y * BM;
    int n0 = blockIdx.x * BN;

    float acc[8][4];
#pragma unroll
    for (int i = 0; i < 8; ++i)
#pragma unroll
        for (int j = 0; j < 4; ++j) acc[i][j] = 0.f;

    for (int t = 0; t < K; t += BK) {
        // load A tile (transposed into As)
#pragma unroll
        for (int l = 0; l < 2; ++l) {
            int e   = tid + l * 256;           // 0..511
            int row = e >> 2, kq = e & 3;
            float4 va = *(const float4*)(A + (size_t)(m0 + row) * K + t + kq * 4);
            As[(kq * 4 + 0) * AS_LD + row] = va.x;
            As[(kq * 4 + 1) * AS_LD + row] = va.y;
            As[(kq * 4 + 2) * AS_LD + row] = va.z;
            As[(kq * 4 + 3) * AS_LD + row] = va.w;
        }
        {
            int row = tid >> 4, nq = tid & 15;
            float4 vb = *(const float4*)(B + (size_t)(t + row) * N + n0 + nq * 4);
            *(float4*)&Bs[row * BN + nq * 4] = vb;
        }
        __syncthreads();

#pragma unroll
        for (int kk = 0; kk < BK; ++kk) {
            float4 a0 = *(float4*)&As[kk * AS_LD + ty * 8];
            float4 a1 = *(float4*)&As[kk * AS_LD + ty * 8 + 4];
            float4 b0 = *(float4*)&Bs[kk * BN + tx * 4];
            float a[8] = {a0.x, a0.y, a0.z, a0.w, a1.x, a1.y, a1.z, a1.w};
            float bb[4] = {b0.x, b0.y, b0.z, b0.w};
#pragma unroll
            for (int i = 0; i < 8; ++i)
#pragma unroll
                for (int j = 0; j < 4; ++j) acc[i][j] += a[i] * bb[j];
        }
        __syncthreads();
    }

    float bs[4];
#pragma unroll
    for (int j = 0; j < 4; ++j) bs[j] = bias[n0 + tx * 4 + j];

#pragma unroll
    for (int i = 0; i < 8; ++i) {
        int m = m0 + ty * 8 + i;
        float4 o;
        float vv[4];
#pragma unroll
        for (int j = 0; j < 4; ++j) {
            float v = acc[i][j] + bs[j];
            if (GELU) v = 0.5f * v * (1.f + erff(v * 0.70710678118654752f));
            vv[j] = v;
        }
        o.x = vv[0]; o.y = vv[1]; o.z = vv[2]; o.w = vv[3];
        *(float4*)(C + (size_t)m * N + n0 + tx * 4) = o;
    }
}

// ---------------------------------------------------------------------------
// K3: windowed attention. One block per (window, head). 128 threads.
// S = (Q*scale) K^T + rel_bias + shift_mask ; softmax ; O = P V.
// ---------------------------------------------------------------------------
__global__ __launch_bounds__(128)
void attn_kernel(const float* __restrict__ qkv,
                 const float* __restrict__ rel_bias,
                 float* __restrict__ ao) {
    __shared__ float qs[NWIN * 33], ks[NWIN * 33], vs[NWIN * 33];
    __shared__ float prow[4][64];
    __shared__ int   cls[NWIN];

    int blk = blockIdx.x;
    int h = blk % HEADS, w = blk / HEADS;
    int widx = w & 63;
    int wi = widx >> 3, wj = widx & 7;
    int r0 = w * NWIN;
    int tid = threadIdx.x, warp = tid >> 5, lane = tid & 31;

    for (int e = tid; e < NWIN * HD; e += 128) {
        int t = e >> 5, d = e & 31;
        const float* base = qkv + (size_t)(r0 + t) * 576 + h * HD + d;
        qs[t * 33 + d] = base[0] * SCALE_Q;
        ks[t * 33 + d] = base[192];
        vs[t * 33 + d] = base[384];
    }
    if (tid < NWIN) {
        int i = tid / WS, j = tid % WS;
        int ry = (wi < 7) ? 0 : ((i < WS - SHIFTV) ? 1 : 2);
        int rx = (wj < 7) ? 0 : ((j < WS - SHIFTV) ? 1 : 2);
        cls[tid] = ry * 3 + rx;
    }
    __syncthreads();

    for (int q = warp; q < NWIN; q += 4) {
        int c1 = lane;
        int c2 = lane + 32;
        bool has2 = (c2 < NWIN);
        int c2c = has2 ? c2 : (NWIN - 1);

        float s1 = 0.f, s2 = 0.f;
#pragma unroll
        for (int d = 0; d < HD; ++d) {
            float qv = qs[q * 33 + d];
            s1 += qv * ks[c1  * 33 + d];
            s2 += qv * ks[c2c * 33 + d];
        }
        int qi = q / WS, qj = q % WS;
        {
            int ki = c1 / WS, kj = c1 % WS;
            s1 += rel_bias[((qi - ki + 6) * 13 + (qj - kj + 6)) * HEADS + h];
            ki = c2c / WS; kj = c2c % WS;
            s2 += rel_bias[((qi - ki + 6) * 13 + (qj - kj + 6)) * HEADS + h];
        }
        int cq = cls[q];
        if (cls[c1] != cq) s1 = -1e30f;
        if (!has2 || cls[c2c] != cq) s2 = -1e30f;

        float mx = fmaxf(s1, s2);
#pragma unroll
        for (int o = 16; o; o >>= 1) mx = fmaxf(mx, __shfl_xor_sync(0xffffffffu, mx, o));
        float e1 = __expf(s1 - mx);
        float e2 = has2 ? __expf(s2 - mx) : 0.f;
        float sum = e1 + e2;
#pragma unroll
        for (int o = 16; o; o >>= 1) sum += __shfl_xor_sync(0xffffffffu, sum, o);
        float inv = 1.f / sum;

        prow[warp][lane]      = e1 * inv;
        prow[warp][lane + 32] = e2 * inv;
        __syncwarp();

        float acc = 0.f;
#pragma unroll
        for (int k = 0; k < NWIN; ++k) acc += prow[warp][k] * vs[k * 33 + lane];
        ao[(size_t)(r0 + q) * DIM + h * HD + lane] = acc;
        __syncwarp();
    }
}

// ---------------------------------------------------------------------------
// K5: x1 = x + window-reverse(roll +3)(proj_out);  h2 = LN2(x1)
// Block = 32 consecutive pixels, smem-transpose tile; all accesses coalesced.
// Output pixel (y,x) receives proj-out from window pos ((y-3)%56,(x-3)%56).
// ---------------------------------------------------------------------------
__global__ __launch_bounds__(256)
void addln2_kernel(const float* __restrict__ x,
                   const float* __restrict__ po,
                   const float* __restrict__ gam,
                   const float* __restrict__ bet,
                   float* __restrict__ x1,
                   float* __restrict__ h2) {
    __shared__ float sm[32][193];
    int p0  = blockIdx.x * 32;
    int b   = p0 / PIX, yx0 = p0 % PIX;
    int tid = threadIdx.x, warp = tid >> 5, lane = tid & 31;

    // Phase 1: gather proj-out rows (row-major, coalesced per pixel)
#pragma unroll
    for (int t = 0; t < 4; ++t) {
        int pix = warp * 4 + t;
        int yx = yx0 + pix;
        int y  = yx / HW, xx = yx % HW;
        int y2 = (y  + HW - SHIFTV) % HW;
        int x2 = (xx + HW - SHIFTV) % HW;
        int r  = b * PIX + ((y2 / WS) * NW_GRID + (x2 / WS)) * NWIN
               + (y2 % WS) * WS + (x2 % WS);
        const float* pp = po + (size_t)r * DIM;
#pragma unroll
        for (int j = 0; j < 6; ++j) {
            int c = lane + j * 32;
            sm[pix][c] = pp[c];
        }
    }
    __syncthreads();

    // Phase 2: x1 = x + po (NCHW reads/writes coalesced), keep sum in smem
    const float* xb = x  + (size_t)b * (DIM * PIX) + yx0;
    float*       xo = x1 + (size_t)b * (DIM * PIX) + yx0;
#pragma unroll
    for (int cc = 0; cc < 24; ++cc) {
        int c = warp + cc * 8;
        float v = xb[(size_t)c * PIX + lane] + sm[lane][c];
        xo[(size_t)c * PIX + lane] = v;
        sm[lane][c] = v;
    }
    __syncthreads();

    // Phase 3: LN2 per pixel, row-major coalesced write
#pragma unroll
    for (int t = 0; t < 4; ++t) {
        int pix = warp * 4 + t;
        float v[6], s = 0.f, sq = 0.f;
#pragma unroll
        for (int j = 0; j < 6; ++j) {
            float u = sm[pix][lane + j * 32];
            v[j] = u; s += u; sq += u * u;
        }
#pragma unroll
        for (int o = 16; o; o >>= 1) {
            s  += __shfl_xor_sync(0xffffffffu, s,  o);
            sq += __shfl_xor_sync(0xffffffffu, sq, o);
        }
        float mu   = s * (1.f / DIM);
        float var  = sq * (1.f / DIM) - mu * mu;
        float rstd = rsqrtf(var + 1e-5f);

        float* hp = h2 + (size_t)(p0 + pix) * DIM;
#pragma unroll
        for (int j = 0; j < 6; ++j) {
            int c = lane + j * 32;
            hp[c] = (v[j] - mu) * rstd * gam[c] + bet[c];
        }
    }
}

// ---------------------------------------------------------------------------
// K8: out = x1 + transpose(mlp).  smem-transpose tile (32 pixels x 192 ch):
// all global traffic coalesced.
// ---------------------------------------------------------------------------
__global__ void final_add_kernel(const float* __restrict__ x1,
                                 const float* __restrict__ m,
                                 float* __restrict__ out) {
    __shared__ float sm[32][193];
    int p0 = blockIdx.x * 32;
    int tid = threadIdx.x;

    for (int e = tid; e < 32 * DIM; e += 256) {
        int i = e / DIM, c = e % DIM;
        sm[i][c] = m[(size_t)(p0 + i) * DIM + c];
    }
    __syncthreads();

    int b   = p0 / PIX;
    int yx0 = p0 % PIX;
    int i   = tid & 31, c0 = tid >> 5;       // warp = one channel, 32 pixels
#pragma unroll
    for (int cc = 0; cc < 24; ++cc) {
        int c = c0 + cc * 8;
        size_t o = (size_t)b * (DIM * PIX) + (size_t)c * PIX + yx0 + i;
        out[o] = x1[o] + sm[i][c];
    }
}

// ---------------------------------------------------------------------------
// Launch
// ---------------------------------------------------------------------------
extern "C" void kernel_launch(void* const* d_in, const int* in_sizes, int n_in,
                              void* d_out, int out_size) {
    const float* x      = (const float*)d_in[0];
    const float* n1g    = (const float*)d_in[1];
    const float* n1b    = (const float*)d_in[2];
    const float* qkv_w  = (const float*)d_in[3];
    const float* qkv_b  = (const float*)d_in[4];
    const float* proj_w = (const float*)d_in[5];
    const float* proj_b = (const float*)d_in[6];
    const float* relb   = (const float*)d_in[7];
    const float* n2g    = (const float*)d_in[8];
    const float* n2b    = (const float*)d_in[9];
    const float* fc1_w  = (const float*)d_in[10];
    const float* fc1_b  = (const float*)d_in[11];
    const float* fc2_w  = (const float*)d_in[12];
    const float* fc2_b  = (const float*)d_in[13];
    float* out = (float*)d_out;

    float *ba, *bb, *bc, *bx1, *bg;
    cudaGetSymbolAddress((void**)&ba,  g_bufa);
    cudaGetSymbolAddress((void**)&bb,  g_bufb);
    cudaGetSymbolAddress((void**)&bc,  g_bufc);
    cudaGetSymbolAddress((void**)&bx1, g_x1);
    cudaGetSymbolAddress((void**)&bg,  g_big);

    // 1) LN1 + roll + window partition -> ba = win[50176,192]
    ln1_win_kernel<<<NPIX / 32, 256>>>(x, n1g, n1b, ba);

    // 2) QKV GEMM: [50176,192]x[192,576] -> bg
    sgemm_kernel<0><<<dim3(576 / BN, NPIX / BM), 256>>>(ba, qkv_w, qkv_b, bg,
                                                        NPIX, 576, DIM);
    // 3) attention -> bb = ao[50176,192]
    attn_kernel<<<1024 * HEADS, 128>>>(bg, relb, bb);

    // 4) proj GEMM -> bc
    sgemm_kernel<0><<<dim3(192 / BN, NPIX / BM), 256>>>(bb, proj_w, proj_b, bc,
                                                        NPIX, DIM, DIM);
    // 5) residual + LN2 -> bx1 (NCHW), ba = h2[50176,192]
    addln2_kernel<<<NPIX / 32, 256>>>(x, bc, n2g, n2b, bx1, ba);

    // 6) fc1 + GELU -> bg[50176,768]
    sgemm_kernel<1><<<dim3(768 / BN, NPIX / BM), 256>>>(ba, fc1_w, fc1_b, bg,
                                                        NPIX, 768, DIM);
    // 7) fc2 -> bb[50176,192]
    sgemm_kernel<0><<<dim3(192 / BN, NPIX / BM), 256>>>(bg, fc2_w, fc2_b, bb,
                                                        NPIX, DIM, 768);
    // 8) out = x1 + transpose(mlp)
    final_add_kernel<<<NPIX / 32, 256>>>(bx1, bb, out);
}

// round 6
// speedup vs baseline: 1.7758x; 1.7758x over previous
#include <cuda_runtime.h>
#include <cuda_bf16.h>
#include <math.h>
#include <stdint.h>

// ---------------------------------------------------------------------------
// Problem constants
// ---------------------------------------------------------------------------
#define BATCH   16
#define DIM     192
#define HW      56
#define PIX     3136            // 56*56
#define NPIX    50176           // 16*3136
#define WS      7
#define SHIFTV  3
#define NWIN    49
#define HEADS   6
#define HD      32
#define NW_GRID 8
#define SCALE_Q 0.1767766952966369f

// ---------------------------------------------------------------------------
// Scratch buffers (allocation-free: device globals)
// ---------------------------------------------------------------------------
__device__ __align__(128) float g_bufa [NPIX * DIM];   // win (LN1 out) / h2 (LN2 out)
__device__ __align__(128) float g_bufb [NPIX * DIM];   // attn out / fc2 out
__device__ __align__(128) float g_bufc [NPIX * DIM];   // proj out
__device__ __align__(128) float g_x1   [NPIX * DIM];   // residual-1 (NCHW)
__device__ __align__(128) float g_big  [NPIX * 768];   // qkv (576 cols) / fc1 out
// transposed weights Wt[N][K]
__device__ __align__(128) float g_qkv_wt [576 * 192];
__device__ __align__(128) float g_proj_wt[192 * 192];
__device__ __align__(128) float g_fc1_wt [768 * 192];
__device__ __align__(128) float g_fc2_wt [192 * 768];

// ---------------------------------------------------------------------------
// mma.sync tf32 helpers (sm_80-era PTX; compiles for plain sm_103,
// executes on the tensor pipe as HMMA fallback)
// ---------------------------------------------------------------------------
__device__ __forceinline__ void mma_tf32(float c[4], const uint32_t a[4],
                                         const uint32_t b[2]) {
    asm volatile(
        "mma.sync.aligned.m16n8k8.row.col.f32.tf32.tf32.f32 "
        "{%0,%1,%2,%3}, {%4,%5,%6,%7}, {%8,%9}, {%0,%1,%2,%3};"
        : "+f"(c[0]), "+f"(c[1]), "+f"(c[2]), "+f"(c[3])
        : "r"(a[0]), "r"(a[1]), "r"(a[2]), "r"(a[3]),
          "r"(b[0]), "r"(b[1]));
}
__device__ __forceinline__ uint32_t f2tf32(float x) {
    uint32_t u;
    asm("cvt.rna.tf32.f32 %0, %1;" : "=r"(u) : "f"(x));
    return u;
}
__device__ __forceinline__ void store_tf32_4(float* dst, float4 v) {
    uint4 o;
    o.x = f2tf32(v.x); o.y = f2tf32(v.y); o.z = f2tf32(v.z); o.w = f2tf32(v.w);
    *(uint4*)dst = o;
}

// ---------------------------------------------------------------------------
// Tensor-core GEMM: C[M,Ntot] = A[M,K] @ Wt[N,K]^T + bias (optional GELU).
// BM=128, BN=64, BK=32; 256 threads = 8 warps (4 M x 2 N), warp tile 32x32.
// smem As[m][k] / Bs[n][k] stride 36 -> conflict-free fragment LDS.
// Double-buffered; K % 32 == 0, M % 128 == 0, Ntot % 64 == 0 (all hold).
// ---------------------------------------------------------------------------
#define BM 128
#define BN 64
#define BKC 32
#define LDA 36                       // padded float stride (144 B, 16B-aligned)
#define SM_FLOATS ((BM * LDA + BN * LDA) * 2)   // 13824 floats = 55296 B

__global__ __launch_bounds__(256, 2)
void mma_gemm(const float* __restrict__ A, const float* __restrict__ Bt,
              const float* __restrict__ bias, float* __restrict__ C,
              int Ntot, int K, int gelu) {
    extern __shared__ float sh[];
    float* As0 = sh;
    float* Bs0 = As0 + BM * LDA;
    float* As1 = Bs0 + BN * LDA;
    float* Bs1 = As1 + BM * LDA;
    __shared__ float sbias[BN];

    int tid = threadIdx.x, lane = tid & 31, wid = tid >> 5;
    int wm = wid & 3, wn = wid >> 2;               // warp coords (M, N)
    int m0 = blockIdx.y * BM;
    int n0 = blockIdx.x * BN;

    if (tid < BN) sbias[tid] = bias[n0 + tid];

    float acc[2][4][4];
#pragma unroll
    for (int i = 0; i < 2; ++i)
#pragma unroll
        for (int j = 0; j < 4; ++j)
#pragma unroll
            for (int l = 0; l < 4; ++l) acc[i][j][l] = 0.f;

    const int S = K / BKC;

    // stage 0 -> buffer 0
#pragma unroll
    for (int i = 0; i < 4; ++i) {
        int e = i * 256 + tid, r = e >> 3, sg = e & 7;
        float4 v = *(const float4*)(A + (size_t)(m0 + r) * K + sg * 4);
        store_tf32_4(As0 + r * LDA + sg * 4, v);
    }
#pragma unroll
    for (int i = 0; i < 2; ++i) {
        int e = i * 256 + tid, r = e >> 3, sg = e & 7;
        float4 v = *(const float4*)(Bt + (size_t)(n0 + r) * K + sg * 4);
        store_tf32_4(Bs0 + r * LDA + sg * 4, v);
    }
    __syncthreads();

    int am = wm * 32 + (lane >> 2);                // A fragment row base
    int bn = wn * 32 + (lane >> 2);                // B fragment row base
    int kq = lane & 3;                             // fragment k offset

    float4 ra[4], rb[2];
    for (int s = 0; s < S; ++s) {
        const float* Acur = (s & 1) ? As1 : As0;
        const float* Bcur = (s & 1) ? Bs1 : Bs0;
        float* Anxt = (s & 1) ? As0 : As1;
        float* Bnxt = (s & 1) ? Bs0 : Bs1;

        bool more = (s + 1 < S);
        if (more) {
            int kc = (s + 1) * BKC;
#pragma unroll
            for (int i = 0; i < 4; ++i) {
                int e = i * 256 + tid, r = e >> 3, sg = e & 7;
                ra[i] = *(const float4*)(A + (size_t)(m0 + r) * K + kc + sg * 4);
            }
#pragma unroll
            for (int i = 0; i < 2; ++i) {
                int e = i * 256 + tid, r = e >> 3, sg = e & 7;
                rb[i] = *(const float4*)(Bt + (size_t)(n0 + r) * K + kc + sg * 4);
            }
        }

#pragma unroll
        for (int ks = 0; ks < 4; ++ks) {
            int kb = ks * 8 + kq;
            uint32_t af[2][4], bf[4][2];
#pragma unroll
            for (int tm = 0; tm < 2; ++tm) {
                int m = am + tm * 16;
                af[tm][0] = __float_as_uint(Acur[m * LDA + kb]);
                af[tm][1] = __float_as_uint(Acur[(m + 8) * LDA + kb]);
                af[tm][2] = __float_as_uint(Acur[m * LDA + kb + 4]);
                af[tm][3] = __float_as_uint(Acur[(m + 8) * LDA + kb + 4]);
            }
#pragma unroll
            for (int tn = 0; tn < 4; ++tn) {
                int n = bn + tn * 8;
                // note: fragment needs n = base + lane>>2 within 8-wide tile
                bf[tn][0] = __float_as_uint(Bcur[(wn * 32 + tn * 8 + (lane >> 2) % 8) * LDA + kb]);
                bf[tn][1] = __float_as_uint(Bcur[(wn * 32 + tn * 8 + (lane >> 2) % 8) * LDA + kb + 4]);
                (void)n;
            }
#pragma unroll
            for (int tm = 0; tm < 2; ++tm)
#pragma unroll
                for (int tn = 0; tn < 4; ++tn)
                    mma_tf32(acc[tm][tn], af[tm], bf[tn]);
        }

        if (more) {
#pragma unroll
            for (int i = 0; i < 4; ++i) {
                int e = i * 256 + tid, r = e >> 3, sg = e & 7;
                store_tf32_4(Anxt + r * LDA + sg * 4, ra[i]);
            }
#pragma unroll
            for (int i = 0; i < 2; ++i) {
                int e = i * 256 + tid, r = e >> 3, sg = e & 7;
                store_tf32_4(Bnxt + r * LDA + sg * 4, rb[i]);
            }
        }
        __syncthreads();
    }

    // ---- epilogue: C fragments -> global, +bias (+GELU) ----
#pragma unroll
    for (int tm = 0; tm < 2; ++tm) {
        int r = m0 + wm * 32 + tm * 16 + (lane >> 2);
#pragma unroll
        for (int tn = 0; tn < 4; ++tn) {
            int cl = wn * 32 + tn * 8 + (kq << 1);        // local col in [0,64)
            float b0 = sbias[cl], b1 = sbias[cl + 1];
            float v0 = acc[tm][tn][0] + b0;
            float v1 = acc[tm][tn][1] + b1;
            float v2 = acc[tm][tn][2] + b0;
            float v3 = acc[tm][tn][3] + b1;
            if (gelu) {
                v0 = 0.5f * v0 * (1.f + erff(v0 * 0.70710678118654752f));
                v1 = 0.5f * v1 * (1.f + erff(v1 * 0.70710678118654752f));
                v2 = 0.5f * v2 * (1.f + erff(v2 * 0.70710678118654752f));
                v3 = 0.5f * v3 * (1.f + erff(v3 * 0.70710678118654752f));
            }
            *(float2*)(C + (size_t)r * Ntot + n0 + cl)       = make_float2(v0, v1);
            *(float2*)(C + (size_t)(r + 8) * Ntot + n0 + cl) = make_float2(v2, v3);
        }
    }
}

// ---------------------------------------------------------------------------
// Weight transpose: W[K][N] -> Wt[N][K].  grid (N/32, K/32), block (32, 8)
// ---------------------------------------------------------------------------
__global__ void transpose_kernel(const float* __restrict__ W,
                                 float* __restrict__ Wt, int K, int N) {
    __shared__ float t[32][33];
    int k0 = blockIdx.y * 32, n0 = blockIdx.x * 32;
    int tx = threadIdx.x, ty = threadIdx.y;
#pragma unroll
    for (int i = 0; i < 32; i += 8)
        t[ty + i][tx] = W[(size_t)(k0 + ty + i) * N + n0 + tx];
    __syncthreads();
#pragma unroll
    for (int i = 0; i < 32; i += 8)
        Wt[(size_t)(n0 + ty + i) * K + k0 + tx] = t[tx][ty + i];
}

// ---------------------------------------------------------------------------
// K1: LayerNorm1 + roll(-3,-3) + window partition
// ---------------------------------------------------------------------------
__global__ __launch_bounds__(256)
void ln1_win_kernel(const float* __restrict__ x,
                    const float* __restrict__ gam,
                    const float* __restrict__ bet,
                    float* __restrict__ win) {
    __shared__ float sm[32][193];
    int p0  = blockIdx.x * 32;
    int b   = p0 / PIX, yx0 = p0 % PIX;
    int tid = threadIdx.x, warp = tid >> 5, lane = tid & 31;

    const float* xb = x + (size_t)b * (DIM * PIX) + yx0;
#pragma unroll
    for (int cc = 0; cc < 24; ++cc) {
        int c = warp + cc * 8;
        sm[lane][c] = xb[(size_t)c * PIX + lane];
    }
    __syncthreads();

#pragma unroll
    for (int t = 0; t < 4; ++t) {
        int pix = warp * 4 + t;
        float v[6], s = 0.f, sq = 0.f;
#pragma unroll
        for (int j = 0; j < 6; ++j) {
            float u = sm[pix][lane + j * 32];
            v[j] = u; s += u; sq += u * u;
        }
#pragma unroll
        for (int o = 16; o; o >>= 1) {
            s  += __shfl_xor_sync(0xffffffffu, s,  o);
            sq += __shfl_xor_sync(0xffffffffu, sq, o);
        }
        float mu   = s * (1.f / DIM);
        float var  = sq * (1.f / DIM) - mu * mu;
        float rstd = rsqrtf(var + 1e-5f);

        int yx = yx0 + pix;
        int y  = yx / HW, xx = yx % HW;
        int y2 = (y  + HW - SHIFTV) % HW;
        int x2 = (xx + HW - SHIFTV) % HW;
        int r  = b * PIX + ((y2 / WS) * NW_GRID + (x2 / WS)) * NWIN
               + (y2 % WS) * WS + (x2 % WS);
        float* wp = win + (size_t)r * DIM;
#pragma unroll
        for (int j = 0; j < 6; ++j) {
            int c = lane + j * 32;
            wp[c] = (v[j] - mu) * rstd * gam[c] + bet[c];
        }
    }
}

// ---------------------------------------------------------------------------
// K3: windowed attention
// ---------------------------------------------------------------------------
__global__ __launch_bounds__(128)
void attn_kernel(const float* __restrict__ qkv,
                 const float* __restrict__ rel_bias,
                 float* __restrict__ ao) {
    __shared__ float qs[NWIN * 33], ks[NWIN * 33], vs[NWIN * 33];
    __shared__ float prow[4][64];
    __shared__ int   cls[NWIN];

    int blk = blockIdx.x;
    int h = blk % HEADS, w = blk / HEADS;
    int widx = w & 63;
    int wi = widx >> 3, wj = widx & 7;
    int r0 = w * NWIN;
    int tid = threadIdx.x, warp = tid >> 5, lane = tid & 31;

    for (int e = tid; e < NWIN * HD; e += 128) {
        int t = e >> 5, d = e & 31;
        const float* base = qkv + (size_t)(r0 + t) * 576 + h * HD + d;
        qs[t * 33 + d] = base[0] * SCALE_Q;
        ks[t * 33 + d] = base[192];
        vs[t * 33 + d] = base[384];
    }
    if (tid < NWIN) {
        int i = tid / WS, j = tid % WS;
        int ry = (wi < 7) ? 0 : ((i < WS - SHIFTV) ? 1 : 2);
        int rx = (wj < 7) ? 0 : ((j < WS - SHIFTV) ? 1 : 2);
        cls[tid] = ry * 3 + rx;
    }
    __syncthreads();

    for (int q = warp; q < NWIN; q += 4) {
        int c1 = lane;
        int c2 = lane + 32;
        bool has2 = (c2 < NWIN);
        int c2c = has2 ? c2 : (NWIN - 1);

        float s1 = 0.f, s2 = 0.f;
#pragma unroll
        for (int d = 0; d < HD; ++d) {
            float qv = qs[q * 33 + d];
            s1 += qv * ks[c1  * 33 + d];
            s2 += qv * ks[c2c * 33 + d];
        }
        int qi = q / WS, qj = q % WS;
        {
            int ki = c1 / WS, kj = c1 % WS;
            s1 += rel_bias[((qi - ki + 6) * 13 + (qj - kj + 6)) * HEADS + h];
            ki = c2c / WS; kj = c2c % WS;
            s2 += rel_bias[((qi - ki + 6) * 13 + (qj - kj + 6)) * HEADS + h];
        }
        int cq = cls[q];
        if (cls[c1] != cq) s1 = -1e30f;
        if (!has2 || cls[c2c] != cq) s2 = -1e30f;

        float mx = fmaxf(s1, s2);
#pragma unroll
        for (int o = 16; o; o >>= 1) mx = fmaxf(mx, __shfl_xor_sync(0xffffffffu, mx, o));
        float e1 = __expf(s1 - mx);
        float e2 = has2 ? __expf(s2 - mx) : 0.f;
        float sum = e1 + e2;
#pragma unroll
        for (int o = 16; o; o >>= 1) sum += __shfl_xor_sync(0xffffffffu, sum, o);
        float inv = 1.f / sum;

        prow[warp][lane]      = e1 * inv;
        prow[warp][lane + 32] = e2 * inv;
        __syncwarp();

        float acc = 0.f;
#pragma unroll
        for (int k = 0; k < NWIN; ++k) acc += prow[warp][k] * vs[k * 33 + lane];
        ao[(size_t)(r0 + q) * DIM + h * HD + lane] = acc;
        __syncwarp();
    }
}

// ---------------------------------------------------------------------------
// K5: x1 = x + window-reverse(proj_out);  h2 = LN2(x1)
// ---------------------------------------------------------------------------
__global__ __launch_bounds__(256)
void addln2_kernel(const float* __restrict__ x,
                   const float* __restrict__ po,
                   const float* __restrict__ gam,
                   const float* __restrict__ bet,
                   float* __restrict__ x1,
                   float* __restrict__ h2) {
    __shared__ float sm[32][193];
    int p0  = blockIdx.x * 32;
    int b   = p0 / PIX, yx0 = p0 % PIX;
    int tid = threadIdx.x, warp = tid >> 5, lane = tid & 31;

#pragma unroll
    for (int t = 0; t < 4; ++t) {
        int pix = warp * 4 + t;
        int yx = yx0 + pix;
        int y  = yx / HW, xx = yx % HW;
        int y2 = (y  + HW - SHIFTV) % HW;
        int x2 = (xx + HW - SHIFTV) % HW;
        int r  = b * PIX + ((y2 / WS) * NW_GRID + (x2 / WS)) * NWIN
               + (y2 % WS) * WS + (x2 % WS);
        const float* pp = po + (size_t)r * DIM;
#pragma unroll
        for (int j = 0; j < 6; ++j) {
            int c = lane + j * 32;
            sm[pix][c] = pp[c];
        }
    }
    __syncthreads();

    const float* xb = x  + (size_t)b * (DIM * PIX) + yx0;
    float*       xo = x1 + (size_t)b * (DIM * PIX) + yx0;
#pragma unroll
    for (int cc = 0; cc < 24; ++cc) {
        int c = warp + cc * 8;
        float v = xb[(size_t)c * PIX + lane] + sm[lane][c];
        xo[(size_t)c * PIX + lane] = v;
        sm[lane][c] = v;
    }
    __syncthreads();

#pragma unroll
    for (int t = 0; t < 4; ++t) {
        int pix = warp * 4 + t;
        float v[6], s = 0.f, sq = 0.f;
#pragma unroll
        for (int j = 0; j < 6; ++j) {
            float u = sm[pix][lane + j * 32];
            v[j] = u; s += u; sq += u * u;
        }
#pragma unroll
        for (int o = 16; o; o >>= 1) {
            s  += __shfl_xor_sync(0xffffffffu, s,  o);
            sq += __shfl_xor_sync(0xffffffffu, sq, o);
        }
        float mu   = s * (1.f / DIM);
        float var  = sq * (1.f / DIM) - mu * mu;
        float rstd = rsqrtf(var + 1e-5f);

        float* hp = h2 + (size_t)(p0 + pix) * DIM;
#pragma unroll
        for (int j = 0; j < 6; ++j) {
            int c = lane + j * 32;
            hp[c] = (v[j] - mu) * rstd * gam[c] + bet[c];
        }
    }
}

// ---------------------------------------------------------------------------
// K8: out = x1 + transpose(mlp)
// ---------------------------------------------------------------------------
__global__ void final_add_kernel(const float* __restrict__ x1,
                                 const float* __restrict__ m,
                                 float* __restrict__ out) {
    __shared__ float sm[32][193];
    int p0 = blockIdx.x * 32;
    int tid = threadIdx.x;

    for (int e = tid; e < 32 * DIM; e += 256) {
        int i = e / DIM, c = e % DIM;
        sm[i][c] = m[(size_t)(p0 + i) * DIM + c];
    }
    __syncthreads();

    int b   = p0 / PIX;
    int yx0 = p0 % PIX;
    int i   = tid & 31, c0 = tid >> 5;
#pragma unroll
    for (int cc = 0; cc < 24; ++cc) {
        int c = c0 + cc * 8;
        size_t o = (size_t)b * (DIM * PIX) + (size_t)c * PIX + yx0 + i;
        out[o] = x1[o] + sm[i][c];
    }
}

// ---------------------------------------------------------------------------
// Launch
// ---------------------------------------------------------------------------
extern "C" void kernel_launch(void* const* d_in, const int* in_sizes, int n_in,
                              void* d_out, int out_size) {
    const float* x      = (const float*)d_in[0];
    const float* n1g    = (const float*)d_in[1];
    const float* n1b    = (const float*)d_in[2];
    const float* qkv_w  = (const float*)d_in[3];
    const float* qkv_b  = (const float*)d_in[4];
    const float* proj_w = (const float*)d_in[5];
    const float* proj_b = (const float*)d_in[6];
    const float* relb   = (const float*)d_in[7];
    const float* n2g    = (const float*)d_in[8];
    const float* n2b    = (const float*)d_in[9];
    const float* fc1_w  = (const float*)d_in[10];
    const float* fc1_b  = (const float*)d_in[11];
    const float* fc2_w  = (const float*)d_in[12];
    const float* fc2_b  = (const float*)d_in[13];
    float* out = (float*)d_out;

    float *ba, *bb, *bc, *bx1, *bg, *wqkv, *wproj, *wfc1, *wfc2;
    cudaGetSymbolAddress((void**)&ba,   g_bufa);
    cudaGetSymbolAddress((void**)&bb,   g_bufb);
    cudaGetSymbolAddress((void**)&bc,   g_bufc);
    cudaGetSymbolAddress((void**)&bx1,  g_x1);
    cudaGetSymbolAddress((void**)&bg,   g_big);
    cudaGetSymbolAddress((void**)&wqkv, g_qkv_wt);
    cudaGetSymbolAddress((void**)&wproj,g_proj_wt);
    cudaGetSymbolAddress((void**)&wfc1, g_fc1_wt);
    cudaGetSymbolAddress((void**)&wfc2, g_fc2_wt);

    const int smem = SM_FLOATS * 4;   // 55296 B
    cudaFuncSetAttribute(mma_gemm, cudaFuncAttributeMaxDynamicSharedMemorySize,
                         smem);

    // 0) weight transposes (tiny)
    transpose_kernel<<<dim3(576 / 32, 192 / 32), dim3(32, 8)>>>(qkv_w,  wqkv, 192, 576);
    transpose_kernel<<<dim3(192 / 32, 192 / 32), dim3(32, 8)>>>(proj_w, wproj,192, 192);
    transpose_kernel<<<dim3(768 / 32, 192 / 32), dim3(32, 8)>>>(fc1_w,  wfc1, 192, 768);
    transpose_kernel<<<dim3(192 / 32, 768 / 32), dim3(32, 8)>>>(fc2_w,  wfc2, 768, 192);

    // 1) LN1 + roll + window partition -> ba = win[50176,192]
    ln1_win_kernel<<<NPIX / 32, 256>>>(x, n1g, n1b, ba);

    // 2) QKV GEMM -> bg[50176,576]
    mma_gemm<<<dim3(576 / BN, NPIX / BM), 256, smem>>>(ba, wqkv, qkv_b, bg,
                                                       576, 192, 0);
    // 3) attention -> bb[50176,192]
    attn_kernel<<<1024 * HEADS, 128>>>(bg, relb, bb);

    // 4) proj GEMM -> bc
    mma_gemm<<<dim3(192 / BN, NPIX / BM), 256, smem>>>(bb, wproj, proj_b, bc,
                                                       192, 192, 0);
    // 5) residual + LN2 -> bx1 (NCHW), ba = h2
    addln2_kernel<<<NPIX / 32, 256>>>(x, bc, n2g, n2b, bx1, ba);

    // 6) fc1 + GELU -> bg[50176,768]
    mma_gemm<<<dim3(768 / BN, NPIX / BM), 256, smem>>>(ba, wfc1, fc1_b, bg,
                                                       768, 192, 1);
    // 7) fc2 -> bb[50176,192]
    mma_gemm<<<dim3(192 / BN, NPIX / BM), 256, smem>>>(bg, wfc2, fc2_b, bb,
                                                       192, 768, 0);
    // 8) out = x1 + transpose(mlp)
    final_add_kernel<<<NPIX / 32, 256>>>(bx1, bb, out);
}

// round 7
// speedup vs baseline: 2.4655x; 1.3884x over previous
#include <cuda_runtime.h>
#include <cuda_bf16.h>
#include <math.h>
#include <stdint.h>

// ---------------------------------------------------------------------------
// Problem constants
// ---------------------------------------------------------------------------
#define BATCH   16
#define DIM     192
#define HW      56
#define PIX     3136            // 56*56
#define NPIX    50176           // 16*3136
#define WS      7
#define SHIFTV  3
#define NWIN    49
#define HEADS   6
#define HD      32
#define NW_GRID 8
#define SCALE_Q 0.1767766952966369f

typedef __nv_bfloat16 bf16;

// ---------------------------------------------------------------------------
// Scratch buffers (allocation-free: device globals)
// ---------------------------------------------------------------------------
__device__ __align__(128) bf16  gb_a   [NPIX * DIM];   // win (ln1 out) / h2 (ln2 out)
__device__ __align__(128) bf16  gb_b   [NPIX * DIM];   // attn out
__device__ __align__(128) bf16  gb_big [NPIX * 768];   // qkv out (576 used) / fc1 out
__device__ __align__(128) float g_projo[NPIX * DIM];   // proj out (fp32)
__device__ __align__(128) float g_x1   [NPIX * DIM];   // residual-1 (NCHW)
__device__ __align__(128) float g_mlp  [NPIX * DIM];   // fc2 out (fp32)
// transposed bf16 weights Wt[N][K]
__device__ __align__(128) bf16 g_qkv_wt [576 * 192];
__device__ __align__(128) bf16 g_proj_wt[192 * 192];
__device__ __align__(128) bf16 g_fc1_wt [768 * 192];
__device__ __align__(128) bf16 g_fc2_wt [192 * 768];

// ---------------------------------------------------------------------------
// PTX helpers
// ---------------------------------------------------------------------------
__device__ __forceinline__ void mma_bf16(float c[4], const uint32_t a[4],
                                         const uint32_t b[2]) {
    asm volatile(
        "mma.sync.aligned.m16n8k16.row.col.f32.bf16.bf16.f32 "
        "{%0,%1,%2,%3}, {%4,%5,%6,%7}, {%8,%9}, {%0,%1,%2,%3};"
        : "+f"(c[0]), "+f"(c[1]), "+f"(c[2]), "+f"(c[3])
        : "r"(a[0]), "r"(a[1]), "r"(a[2]), "r"(a[3]),
          "r"(b[0]), "r"(b[1]));
}
__device__ __forceinline__ void cp16(uint32_t dst, const void* src) {
    asm volatile("cp.async.cg.shared.global [%0], [%1], 16;"
                 :: "r"(dst), "l"(src));
}
__device__ __forceinline__ void cp_commit() {
    asm volatile("cp.async.commit_group;" ::: "memory");
}
__device__ __forceinline__ void cp_wait0() {
    asm volatile("cp.async.wait_group 0;" ::: "memory");
}
__device__ __forceinline__ uint32_t sptr(const void* p) {
    return (uint32_t)__cvta_generic_to_shared(p);
}

// ---------------------------------------------------------------------------
// bf16 tensor-core GEMM: C[M,Ntot] = A[M,K] @ Wt[N,K]^T + bias
// BM=128, BN=96, BKC=32; 256 threads = 8 warps (4 M x 2 N), warp tile 32x48.
// Smem row = 32 bf16 = 64B = 4 x 16B groups; group g of row r stored at
// g ^ ((r>>1)&3)  -> all fragment LDS.32 and cp.async stores conflict-free.
// MODE: 0 = fp32 out, 1 = bf16+GELU out, 2 = bf16 out.
// ---------------------------------------------------------------------------
#define BM 128
#define BN 96
#define BKC 32

template <int MODE>
__global__ __launch_bounds__(256, 2)
void mma_gemm(const bf16* __restrict__ A, const bf16* __restrict__ Bt,
              const float* __restrict__ bias, void* __restrict__ Cout,
              int Ntot, int K) {
    __shared__ __align__(16) char smA[2][BM * 64];
    __shared__ __align__(16) char smB[2][BN * 64];
    __shared__ float sbias[BN];

    int tid = threadIdx.x, lane = tid & 31, wid = tid >> 5;
    int wm = wid & 3, wn = wid >> 2;           // warp coords: M (0..3), N (0..1)
    int m0 = blockIdx.y * BM;
    int n0 = blockIdx.x * BN;

    if (tid < BN) sbias[tid] = bias[n0 + tid];

    uint32_t aA[2] = { sptr(smA[0]), sptr(smA[1]) };
    uint32_t aB[2] = { sptr(smB[0]), sptr(smB[1]) };

    float acc[2][6][4];
#pragma unroll
    for (int i = 0; i < 2; ++i)
#pragma unroll
        for (int j = 0; j < 6; ++j)
#pragma unroll
            for (int l = 0; l < 4; ++l) acc[i][j][l] = 0.f;

    const int S = K / BKC;

    auto stage = [&](int kc, int buf) {
#pragma unroll
        for (int i = 0; i < 2; ++i) {          // A: 512 16B-groups
            int e = (i << 8) + tid;
            int row = e >> 2, g = e & 3;
            uint32_t dst = aA[buf] + row * 64 + ((g ^ ((row >> 1) & 3)) << 4);
            cp16(dst, A + (size_t)(m0 + row) * K + kc + g * 8);
        }
        {                                       // B: 384 16B-groups
            int row = tid >> 2, g = tid & 3;
            uint32_t dst = aB[buf] + row * 64 + ((g ^ ((row >> 1) & 3)) << 4);
            cp16(dst, Bt + (size_t)(n0 + row) * K + kc + g * 8);
        }
        if (tid < 128) {
            int e = 256 + tid;
            int row = e >> 2, g = e & 3;
            uint32_t dst = aB[buf] + row * 64 + ((g ^ ((row >> 1) & 3)) << 4);
            cp16(dst, Bt + (size_t)(n0 + row) * K + kc + g * 8);
        }
        cp_commit();
    };

    stage(0, 0);

    int q    = lane & 3;
    int swz  = ((lane >> 3) & 3) << 2;         // per-lane swizzle constant (words)
    int rA   = wm * 32 + (lane >> 2);          // A fragment base row
    int rB   = wn * 48 + (lane >> 2);          // B fragment base row

    for (int s = 0; s < S; ++s) {
        int buf = s & 1;
        cp_wait0();
        __syncthreads();
        if (s + 1 < S) stage((s + 1) * BKC, buf ^ 1);

        const char* cA = smA[buf];
        const char* cB = smB[buf];
#pragma unroll
        for (int ks = 0; ks < 2; ++ks) {
            int w1 = ((q + ks * 8) ^ swz) << 2;        // byte offset in row
            int w2 = ((q + 4 + ks * 8) ^ swz) << 2;

            uint32_t af[2][4];
#pragma unroll
            for (int tm = 0; tm < 2; ++tm) {
                int r = rA + tm * 16;
                af[tm][0] = *(const uint32_t*)(cA + r * 64 + w1);
                af[tm][1] = *(const uint32_t*)(cA + (r + 8) * 64 + w1);
                af[tm][2] = *(const uint32_t*)(cA + r * 64 + w2);
                af[tm][3] = *(const uint32_t*)(cA + (r + 8) * 64 + w2);
            }
            uint32_t bfr[6][2];
#pragma unroll
            for (int tn = 0; tn < 6; ++tn) {
                int r = rB + tn * 8;
                bfr[tn][0] = *(const uint32_t*)(cB + r * 64 + w1);
                bfr[tn][1] = *(const uint32_t*)(cB + r * 64 + w2);
            }
#pragma unroll
            for (int tm = 0; tm < 2; ++tm)
#pragma unroll
                for (int tn = 0; tn < 6; ++tn)
                    mma_bf16(acc[tm][tn], af[tm], bfr[tn]);
        }
    }

    // ---- epilogue ----
#pragma unroll
    for (int tm = 0; tm < 2; ++tm) {
        int r = m0 + wm * 32 + tm * 16 + (lane >> 2);
#pragma unroll
        for (int tn = 0; tn < 6; ++tn) {
            int cl = wn * 48 + tn * 8 + (q << 1);
            float b0 = sbias[cl], b1 = sbias[cl + 1];
            float v0 = acc[tm][tn][0] + b0;
            float v1 = acc[tm][tn][1] + b1;
            float v2 = acc[tm][tn][2] + b0;
            float v3 = acc[tm][tn][3] + b1;
            if (MODE == 1) {
                v0 = 0.5f * v0 * (1.f + erff(v0 * 0.70710678118654752f));
                v1 = 0.5f * v1 * (1.f + erff(v1 * 0.70710678118654752f));
                v2 = 0.5f * v2 * (1.f + erff(v2 * 0.70710678118654752f));
                v3 = 0.5f * v3 * (1.f + erff(v3 * 0.70710678118654752f));
            }
            if (MODE == 0) {
                float* C = (float*)Cout;
                *(float2*)(C + (size_t)r * Ntot + n0 + cl)       = make_float2(v0, v1);
                *(float2*)(C + (size_t)(r + 8) * Ntot + n0 + cl) = make_float2(v2, v3);
            } else {
                bf16* C = (bf16*)Cout;
                *(__nv_bfloat162*)(C + (size_t)r * Ntot + n0 + cl) =
                    __floats2bfloat162_rn(v0, v1);
                *(__nv_bfloat162*)(C + (size_t)(r + 8) * Ntot + n0 + cl) =
                    __floats2bfloat162_rn(v2, v3);
            }
        }
    }
}

// ---------------------------------------------------------------------------
// Weight transpose + bf16 convert: W[K][N] -> Wt[N][K]
// ---------------------------------------------------------------------------
__global__ void transpose_kernel(const float* __restrict__ W,
                                 bf16* __restrict__ Wt, int K, int N) {
    __shared__ float t[32][33];
    int k0 = blockIdx.y * 32, n0 = blockIdx.x * 32;
    int tx = threadIdx.x, ty = threadIdx.y;
#pragma unroll
    for (int i = 0; i < 32; i += 8)
        t[ty + i][tx] = W[(size_t)(k0 + ty + i) * N + n0 + tx];
    __syncthreads();
#pragma unroll
    for (int i = 0; i < 32; i += 8)
        Wt[(size_t)(n0 + ty + i) * K + k0 + tx] = __float2bfloat16(t[tx][ty + i]);
}

// ---------------------------------------------------------------------------
// K1: LayerNorm1 + roll(-3,-3) + window partition -> bf16 win
// ---------------------------------------------------------------------------
__global__ __launch_bounds__(256)
void ln1_win_kernel(const float* __restrict__ x,
                    const float* __restrict__ gam,
                    const float* __restrict__ bet,
                    bf16* __restrict__ win) {
    __shared__ float sm[32][193];
    int p0  = blockIdx.x * 32;
    int b   = p0 / PIX, yx0 = p0 % PIX;
    int tid = threadIdx.x, warp = tid >> 5, lane = tid & 31;

    const float* xb = x + (size_t)b * (DIM * PIX) + yx0;
#pragma unroll
    for (int cc = 0; cc < 24; ++cc) {
        int c = warp + cc * 8;
        sm[lane][c] = xb[(size_t)c * PIX + lane];
    }
    __syncthreads();

#pragma unroll
    for (int t = 0; t < 4; ++t) {
        int pix = warp * 4 + t;
        float v[6], s = 0.f, sq = 0.f;
#pragma unroll
        for (int j = 0; j < 6; ++j) {
            float u = sm[pix][lane + j * 32];
            v[j] = u; s += u; sq += u * u;
        }
#pragma unroll
        for (int o = 16; o; o >>= 1) {
            s  += __shfl_xor_sync(0xffffffffu, s,  o);
            sq += __shfl_xor_sync(0xffffffffu, sq, o);
        }
        float mu   = s * (1.f / DIM);
        float var  = sq * (1.f / DIM) - mu * mu;
        float rstd = rsqrtf(var + 1e-5f);

        int yx = yx0 + pix;
        int y  = yx / HW, xx = yx % HW;
        int y2 = (y  + HW - SHIFTV) % HW;
        int x2 = (xx + HW - SHIFTV) % HW;
        int r  = b * PIX + ((y2 / WS) * NW_GRID + (x2 / WS)) * NWIN
               + (y2 % WS) * WS + (x2 % WS);
        bf16* wp = win + (size_t)r * DIM;
#pragma unroll
        for (int j = 0; j < 6; ++j) {
            int c = lane + j * 32;
            wp[c] = __float2bfloat16((v[j] - mu) * rstd * gam[c] + bet[c]);
        }
    }
}

// ---------------------------------------------------------------------------
// K3: windowed attention. qkv in bf16 [row,576], output bf16 [row,192].
// ---------------------------------------------------------------------------
__global__ __launch_bounds__(128)
void attn_kernel(const bf16* __restrict__ qkv,
                 const float* __restrict__ rel_bias,
                 bf16* __restrict__ ao) {
    __shared__ float qs[NWIN * 33], ks[NWIN * 33], vs[NWIN * 33];
    __shared__ float prow[4][64];
    __shared__ int   cls[NWIN];

    int blk = blockIdx.x;
    int h = blk % HEADS, w = blk / HEADS;
    int widx = w & 63;
    int wi = widx >> 3, wj = widx & 7;
    int r0 = w * NWIN;
    int tid = threadIdx.x, warp = tid >> 5, lane = tid & 31;

    for (int e = tid; e < NWIN * HD; e += 128) {
        int t = e >> 5, d = e & 31;
        const bf16* base = qkv + (size_t)(r0 + t) * 576 + h * HD + d;
        qs[t * 33 + d] = __bfloat162float(base[0]) * SCALE_Q;
        ks[t * 33 + d] = __bfloat162float(base[192]);
        vs[t * 33 + d] = __bfloat162float(base[384]);
    }
    if (tid < NWIN) {
        int i = tid / WS, j = tid % WS;
        int ry = (wi < 7) ? 0 : ((i < WS - SHIFTV) ? 1 : 2);
        int rx = (wj < 7) ? 0 : ((j < WS - SHIFTV) ? 1 : 2);
        cls[tid] = ry * 3 + rx;
    }
    __syncthreads();

    for (int q = warp; q < NWIN; q += 4) {
        int c1 = lane;
        int c2 = lane + 32;
        bool has2 = (c2 < NWIN);
        int c2c = has2 ? c2 : (NWIN - 1);

        float s1 = 0.f, s2 = 0.f;
#pragma unroll
        for (int d = 0; d < HD; ++d) {
            float qv = qs[q * 33 + d];
            s1 += qv * ks[c1  * 33 + d];
            s2 += qv * ks[c2c * 33 + d];
        }
        int qi = q / WS, qj = q % WS;
        {
            int ki = c1 / WS, kj = c1 % WS;
            s1 += rel_bias[((qi - ki + 6) * 13 + (qj - kj + 6)) * HEADS + h];
            ki = c2c / WS; kj = c2c % WS;
            s2 += rel_bias[((qi - ki + 6) * 13 + (qj - kj + 6)) * HEADS + h];
        }
        int cq = cls[q];
        if (cls[c1] != cq) s1 = -1e30f;
        if (!has2 || cls[c2c] != cq) s2 = -1e30f;

        float mx = fmaxf(s1, s2);
#pragma unroll
        for (int o = 16; o; o >>= 1) mx = fmaxf(mx, __shfl_xor_sync(0xffffffffu, mx, o));
        float e1 = __expf(s1 - mx);
        float e2 = has2 ? __expf(s2 - mx) : 0.f;
        float sum = e1 + e2;
#pragma unroll
        for (int o = 16; o; o >>= 1) sum += __shfl_xor_sync(0xffffffffu, sum, o);
        float inv = 1.f / sum;

        prow[warp][lane]      = e1 * inv;
        prow[warp][lane + 32] = e2 * inv;
        __syncwarp();

        float acc = 0.f;
#pragma unroll
        for (int k = 0; k < NWIN; ++k) acc += prow[warp][k] * vs[k * 33 + lane];
        ao[(size_t)(r0 + q) * DIM + h * HD + lane] = __float2bfloat16(acc);
        __syncwarp();
    }
}

// ---------------------------------------------------------------------------
// K5: x1 = x + window-reverse(proj_out);  h2 = LN2(x1) -> bf16
// ---------------------------------------------------------------------------
__global__ __launch_bounds__(256)
void addln2_kernel(const float* __restrict__ x,
                   const float* __restrict__ po,
                   const float* __restrict__ gam,
                   const float* __restrict__ bet,
                   float* __restrict__ x1,
                   bf16* __restrict__ h2) {
    __shared__ float sm[32][193];
    int p0  = blockIdx.x * 32;
    int b   = p0 / PIX, yx0 = p0 % PIX;
    int tid = threadIdx.x, warp = tid >> 5, lane = tid & 31;

#pragma unroll
    for (int t = 0; t < 4; ++t) {
        int pix = warp * 4 + t;
        int yx = yx0 + pix;
        int y  = yx / HW, xx = yx % HW;
        int y2 = (y  + HW - SHIFTV) % HW;
        int x2 = (xx + HW - SHIFTV) % HW;
        int r  = b * PIX + ((y2 / WS) * NW_GRID + (x2 / WS)) * NWIN
               + (y2 % WS) * WS + (x2 % WS);
        const float* pp = po + (size_t)r * DIM;
#pragma unroll
        for (int j = 0; j < 6; ++j) {
            int c = lane + j * 32;
            sm[pix][c] = pp[c];
        }
    }
    __syncthreads();

    const float* xb = x  + (size_t)b * (DIM * PIX) + yx0;
    float*       xo = x1 + (size_t)b * (DIM * PIX) + yx0;
#pragma unroll
    for (int cc = 0; cc < 24; ++cc) {
        int c = warp + cc * 8;
        float v = xb[(size_t)c * PIX + lane] + sm[lane][c];
        xo[(size_t)c * PIX + lane] = v;
        sm[lane][c] = v;
    }
    __syncthreads();

#pragma unroll
    for (int t = 0; t < 4; ++t) {
        int pix = warp * 4 + t;
        float v[6], s = 0.f, sq = 0.f;
#pragma unroll
        for (int j = 0; j < 6; ++j) {
            float u = sm[pix][lane + j * 32];
            v[j] = u; s += u; sq += u * u;
        }
#pragma unroll
        for (int o = 16; o; o >>= 1) {
            s  += __shfl_xor_sync(0xffffffffu, s,  o);
            sq += __shfl_xor_sync(0xffffffffu, sq, o);
        }
        float mu   = s * (1.f / DIM);
        float var  = sq * (1.f / DIM) - mu * mu;
        float rstd = rsqrtf(var + 1e-5f);

        bf16* hp = h2 + (size_t)(p0 + pix) * DIM;
#pragma unroll
        for (int j = 0; j < 6; ++j) {
            int c = lane + j * 32;
            hp[c] = __float2bfloat16((v[j] - mu) * rstd * gam[c] + bet[c]);
        }
    }
}

// ---------------------------------------------------------------------------
// K8: out = x1 + transpose(mlp)
// ---------------------------------------------------------------------------
__global__ void final_add_kernel(const float* __restrict__ x1,
                                 const float* __restrict__ m,
                                 float* __restrict__ out) {
    __shared__ float sm[32][193];
    int p0 = blockIdx.x * 32;
    int tid = threadIdx.x;

    for (int e = tid; e < 32 * DIM; e += 256) {
        int i = e / DIM, c = e % DIM;
        sm[i][c] = m[(size_t)(p0 + i) * DIM + c];
    }
    __syncthreads();

    int b   = p0 / PIX;
    int yx0 = p0 % PIX;
    int i   = tid & 31, c0 = tid >> 5;
#pragma unroll
    for (int cc = 0; cc < 24; ++cc) {
        int c = c0 + cc * 8;
        size_t o = (size_t)b * (DIM * PIX) + (size_t)c * PIX + yx0 + i;
        out[o] = x1[o] + sm[i][c];
    }
}

// ---------------------------------------------------------------------------
// Launch
// ---------------------------------------------------------------------------
extern "C" void kernel_launch(void* const* d_in, const int* in_sizes, int n_in,
                              void* d_out, int out_size) {
    const float* x      = (const float*)d_in[0];
    const float* n1g    = (const float*)d_in[1];
    const float* n1b    = (const float*)d_in[2];
    const float* qkv_w  = (const float*)d_in[3];
    const float* qkv_b  = (const float*)d_in[4];
    const float* proj_w = (const float*)d_in[5];
    const float* proj_b = (const float*)d_in[6];
    const float* relb   = (const float*)d_in[7];
    const float* n2g    = (const float*)d_in[8];
    const float* n2b    = (const float*)d_in[9];
    const float* fc1_w  = (const float*)d_in[10];
    const float* fc1_b  = (const float*)d_in[11];
    const float* fc2_w  = (const float*)d_in[12];
    const float* fc2_b  = (const float*)d_in[13];
    float* out = (float*)d_out;

    bf16 *ba, *bb, *bg, *wqkv, *wproj, *wfc1, *wfc2;
    float *bpo, *bx1, *bmlp;
    cudaGetSymbolAddress((void**)&ba,   gb_a);
    cudaGetSymbolAddress((void**)&bb,   gb_b);
    cudaGetSymbolAddress((void**)&bg,   gb_big);
    cudaGetSymbolAddress((void**)&bpo,  g_projo);
    cudaGetSymbolAddress((void**)&bx1,  g_x1);
    cudaGetSymbolAddress((void**)&bmlp, g_mlp);
    cudaGetSymbolAddress((void**)&wqkv, g_qkv_wt);
    cudaGetSymbolAddress((void**)&wproj,g_proj_wt);
    cudaGetSymbolAddress((void**)&wfc1, g_fc1_wt);
    cudaGetSymbolAddress((void**)&wfc2, g_fc2_wt);

    // 0) weight transposes + bf16 convert (tiny)
    transpose_kernel<<<dim3(576 / 32, 192 / 32), dim3(32, 8)>>>(qkv_w,  wqkv, 192, 576);
    transpose_kernel<<<dim3(192 / 32, 192 / 32), dim3(32, 8)>>>(proj_w, wproj,192, 192);
    transpose_kernel<<<dim3(768 / 32, 192 / 32), dim3(32, 8)>>>(fc1_w,  wfc1, 192, 768);
    transpose_kernel<<<dim3(192 / 32, 768 / 32), dim3(32, 8)>>>(fc2_w,  wfc2, 768, 192);

    // 1) LN1 + roll + window partition -> ba = win[50176,192] bf16
    ln1_win_kernel<<<NPIX / 32, 256>>>(x, n1g, n1b, ba);

    // 2) QKV GEMM -> bg[50176,576] bf16
    mma_gemm<2><<<dim3(576 / BN, NPIX / BM), 256>>>(ba, wqkv, qkv_b, bg, 576, 192);

    // 3) attention -> bb[50176,192] bf16
    attn_kernel<<<1024 * HEADS, 128>>>(bg, relb, bb);

    // 4) proj GEMM -> bpo fp32
    mma_gemm<0><<<dim3(192 / BN, NPIX / BM), 256>>>(bb, wproj, proj_b, bpo, 192, 192);

    // 5) residual + LN2 -> bx1 (NCHW fp32), ba = h2 bf16
    addln2_kernel<<<NPIX / 32, 256>>>(x, bpo, n2g, n2b, bx1, ba);

    // 6) fc1 + GELU -> bg[50176,768] bf16
    mma_gemm<1><<<dim3(768 / BN, NPIX / BM), 256>>>(ba, wfc1, fc1_b, bg, 768, 192);

    // 7) fc2 -> bmlp fp32
    mma_gemm<0><<<dim3(192 / BN, NPIX / BM), 256>>>(bg, wfc2, fc2_b, bmlp, 192, 768);

    // 8) out = x1 + transpose(mlp)
    final_add_kernel<<<NPIX / 32, 256>>>(bx1, bmlp, out);
}

// round 8
// speedup vs baseline: 2.6051x; 1.0566x over previous
#include <cuda_runtime.h>
#include <cuda_bf16.h>
#include <math.h>
#include <stdint.h>

// ---------------------------------------------------------------------------
// Problem constants
// ---------------------------------------------------------------------------
#define BATCH   16
#define DIM     192
#define HW      56
#define PIX     3136            // 56*56
#define NPIX    50176           // 16*3136
#define WS      7
#define SHIFTV  3
#define NWIN    49
#define HEADS   6
#define HD      32
#define NW_GRID 8
#define SCALE_Q 0.1767766952966369f

typedef __nv_bfloat16 bf16;

// ---------------------------------------------------------------------------
// Scratch buffers (allocation-free: device globals)
// ---------------------------------------------------------------------------
__device__ __align__(128) bf16  gb_a   [NPIX * DIM];   // win (ln1 out) / h2 (ln2 out)
__device__ __align__(128) bf16  gb_b   [NPIX * DIM];   // attn out
__device__ __align__(128) bf16  gb_big [NPIX * 768];   // qkv out (576 used) / fc1 out
__device__ __align__(128) float g_projo[NPIX * DIM];   // proj out (fp32)
__device__ __align__(128) float g_x1   [NPIX * DIM];   // residual-1 (NCHW)
// transposed bf16 weights Wt[N][K]
__device__ __align__(128) bf16 g_qkv_wt [576 * 192];
__device__ __align__(128) bf16 g_proj_wt[192 * 192];
__device__ __align__(128) bf16 g_fc1_wt [768 * 192];
__device__ __align__(128) bf16 g_fc2_wt [192 * 768];

// ---------------------------------------------------------------------------
// PTX helpers
// ---------------------------------------------------------------------------
__device__ __forceinline__ void mma_bf16(float c[4], const uint32_t a[4],
                                         const uint32_t b0, const uint32_t b1) {
    asm volatile(
        "mma.sync.aligned.m16n8k16.row.col.f32.bf16.bf16.f32 "
        "{%0,%1,%2,%3}, {%4,%5,%6,%7}, {%8,%9}, {%0,%1,%2,%3};"
        : "+f"(c[0]), "+f"(c[1]), "+f"(c[2]), "+f"(c[3])
        : "r"(a[0]), "r"(a[1]), "r"(a[2]), "r"(a[3]),
          "r"(b0), "r"(b1));
}
__device__ __forceinline__ void ldsm4(uint32_t r[4], uint32_t addr) {
    asm volatile("ldmatrix.sync.aligned.m8n8.x4.shared.b16 {%0,%1,%2,%3}, [%4];"
                 : "=r"(r[0]), "=r"(r[1]), "=r"(r[2]), "=r"(r[3]) : "r"(addr));
}
__device__ __forceinline__ void cp16(uint32_t dst, const void* src) {
    asm volatile("cp.async.cg.shared.global [%0], [%1], 16;"
                 :: "r"(dst), "l"(src));
}
__device__ __forceinline__ void cp_commit() {
    asm volatile("cp.async.commit_group;" ::: "memory");
}
__device__ __forceinline__ void cp_wait0() {
    asm volatile("cp.async.wait_group 0;" ::: "memory");
}
__device__ __forceinline__ uint32_t sptr(const void* p) {
    return (uint32_t)__cvta_generic_to_shared(p);
}

// ---------------------------------------------------------------------------
// bf16 tensor-core GEMM: C[M,Ntot] = A[M,K] @ Wt[N,K]^T + bias
// BM=128, BN=96, BKC=32; 256 threads = 8 warps (4 M x 2 N), warp tile 32x48.
// Smem row = 32 bf16 = 64B = 4 x 16B groups; group g of row r stored at
// g ^ ((r>>1)&3)  -> cp.async stores, ldmatrix loads all conflict-free.
// MODE: 0 = fp32 out, 1 = bf16+GELU out, 2 = bf16 out,
//       3 = fp32 NCHW out with fused residual add (out = x1 + acc+bias).
// ---------------------------------------------------------------------------
#define BM 128
#define BN 96
#define BKC 32

template <int MODE>
__global__ __launch_bounds__(256, 2)
void mma_gemm(const bf16* __restrict__ A, const bf16* __restrict__ Bt,
              const float* __restrict__ bias, void* __restrict__ Cout,
              const float* __restrict__ x1aux, int Ntot, int K) {
    __shared__ __align__(16) char smA[2][BM * 64];
    __shared__ __align__(16) char smB[2][BN * 64];
    __shared__ float sbias[BN];

    int tid = threadIdx.x, lane = tid & 31, wid = tid >> 5;
    int wm = wid & 3, wn = wid >> 2;           // warp coords: M (0..3), N (0..1)
    int m0 = blockIdx.y * BM;
    int n0 = blockIdx.x * BN;

    if (tid < BN) sbias[tid] = bias[n0 + tid];

    uint32_t aA[2] = { sptr(smA[0]), sptr(smA[1]) };
    uint32_t aB[2] = { sptr(smB[0]), sptr(smB[1]) };

    float acc[2][6][4];
#pragma unroll
    for (int i = 0; i < 2; ++i)
#pragma unroll
        for (int j = 0; j < 6; ++j)
#pragma unroll
            for (int l = 0; l < 4; ++l) acc[i][j][l] = 0.f;

    const int S = K / BKC;

    auto stage = [&](int kc, int buf) {
#pragma unroll
        for (int i = 0; i < 2; ++i) {          // A: 512 16B-groups
            int e = (i << 8) + tid;
            int row = e >> 2, g = e & 3;
            uint32_t dst = aA[buf] + row * 64 + ((g ^ ((row >> 1) & 3)) << 4);
            cp16(dst, A + (size_t)(m0 + row) * K + kc + g * 8);
        }
        {                                       // B: 384 16B-groups
            int row = tid >> 2, g = tid & 3;
            uint32_t dst = aB[buf] + row * 64 + ((g ^ ((row >> 1) & 3)) << 4);
            cp16(dst, Bt + (size_t)(n0 + row) * K + kc + g * 8);
        }
        if (tid < 128) {
            int e = 256 + tid;
            int row = e >> 2, g = e & 3;
            uint32_t dst = aB[buf] + row * 64 + ((g ^ ((row >> 1) & 3)) << 4);
            cp16(dst, Bt + (size_t)(n0 + row) * K + kc + g * 8);
        }
        cp_commit();
    };

    stage(0, 0);

    // ---- ldmatrix per-lane address components ----
    // A (x4 = m16 x k16): lanes 0-15 rows m..m+15 khalf0, lanes 16-31 khalf1
    uint32_t aRow[2], aSw[2];
    int aHalf = lane >> 4;
#pragma unroll
    for (int tm = 0; tm < 2; ++tm) {
        int r = wm * 32 + tm * 16 + (lane & 15);
        aRow[tm] = r * 64;
        aSw[tm]  = (r >> 1) & 3;
    }
    // B (x4 = two n8-tiles x k16): lanes /16 -> n-tile in pair, (lane>>3)&1 -> khalf
    uint32_t bRow[3], bSw[3];
    int bHalf = (lane >> 3) & 1;
#pragma unroll
    for (int p = 0; p < 3; ++p) {
        int r = wn * 48 + p * 16 + ((lane >> 4) << 3) + (lane & 7);
        bRow[p] = r * 64;
        bSw[p]  = (r >> 1) & 3;
    }

    for (int s = 0; s < S; ++s) {
        int buf = s & 1;
        cp_wait0();
        __syncthreads();
        if (s + 1 < S) stage((s + 1) * BKC, buf ^ 1);

        uint32_t bA = aA[buf], bB = aB[buf];
#pragma unroll
        for (int ks = 0; ks < 2; ++ks) {
            uint32_t af[2][4], bq[3][4];
#pragma unroll
            for (int tm = 0; tm < 2; ++tm)
                ldsm4(af[tm], bA + aRow[tm]
                      + ((((ks << 1) | aHalf) ^ aSw[tm]) << 4));
#pragma unroll
            for (int p = 0; p < 3; ++p)
                ldsm4(bq[p], bB + bRow[p]
                      + ((((ks << 1) | bHalf) ^ bSw[p]) << 4));
#pragma unroll
            for (int tm = 0; tm < 2; ++tm)
#pragma unroll
                for (int tn = 0; tn < 6; ++tn)
                    mma_bf16(acc[tm][tn], af[tm],
                             bq[tn >> 1][(tn & 1) << 1],
                             bq[tn >> 1][((tn & 1) << 1) + 1]);
        }
    }

    // ---- epilogue ----
    int q = lane & 3;
#pragma unroll
    for (int tm = 0; tm < 2; ++tm) {
        int r = m0 + wm * 32 + tm * 16 + (lane >> 2);
        size_t base1 = 0, base2 = 0;
        if (MODE == 3) {
            int b1 = r / PIX, yx1 = r % PIX;
            int r2 = r + 8;
            int b2 = r2 / PIX, yx2 = r2 % PIX;
            base1 = (size_t)b1 * (DIM * PIX) + yx1;
            base2 = (size_t)b2 * (DIM * PIX) + yx2;
        }
#pragma unroll
        for (int tn = 0; tn < 6; ++tn) {
            int cl = wn * 48 + tn * 8 + (q << 1);
            float b0 = sbias[cl], b1v = sbias[cl + 1];
            float v0 = acc[tm][tn][0] + b0;
            float v1 = acc[tm][tn][1] + b1v;
            float v2 = acc[tm][tn][2] + b0;
            float v3 = acc[tm][tn][3] + b1v;
            if (MODE == 1) {
                v0 = 0.5f * v0 * (1.f + erff(v0 * 0.70710678118654752f));
                v1 = 0.5f * v1 * (1.f + erff(v1 * 0.70710678118654752f));
                v2 = 0.5f * v2 * (1.f + erff(v2 * 0.70710678118654752f));
                v3 = 0.5f * v3 * (1.f + erff(v3 * 0.70710678118654752f));
            }
            if (MODE == 0) {
                float* C = (float*)Cout;
                *(float2*)(C + (size_t)r * Ntot + n0 + cl)       = make_float2(v0, v1);
                *(float2*)(C + (size_t)(r + 8) * Ntot + n0 + cl) = make_float2(v2, v3);
            } else if (MODE == 3) {
                float* O = (float*)Cout;
                size_t o00 = base1 + (size_t)(n0 + cl) * PIX;
                size_t o01 = base1 + (size_t)(n0 + cl + 1) * PIX;
                size_t o10 = base2 + (size_t)(n0 + cl) * PIX;
                size_t o11 = base2 + (size_t)(n0 + cl + 1) * PIX;
                O[o00] = x1aux[o00] + v0;
                O[o01] = x1aux[o01] + v1;
                O[o10] = x1aux[o10] + v2;
                O[o11] = x1aux[o11] + v3;
            } else {
                bf16* C = (bf16*)Cout;
                *(__nv_bfloat162*)(C + (size_t)r * Ntot + n0 + cl) =
                    __floats2bfloat162_rn(v0, v1);
                *(__nv_bfloat162*)(C + (size_t)(r + 8) * Ntot + n0 + cl) =
                    __floats2bfloat162_rn(v2, v3);
            }
        }
    }
}

// ---------------------------------------------------------------------------
// All 4 weight transposes (+bf16 convert) in ONE launch: W[K][N] -> Wt[N][K]
// 432 blocks total, block (32, 8).
// ---------------------------------------------------------------------------
__global__ void transpose_all(const float* __restrict__ w0, const float* __restrict__ w1,
                              const float* __restrict__ w2, const float* __restrict__ w3,
                              bf16* __restrict__ t0, bf16* __restrict__ t1,
                              bf16* __restrict__ t2, bf16* __restrict__ t3) {
    __shared__ float t[32][33];
    int bid = blockIdx.x;
    const float* W; bf16* Wt; int K, N, tn, tk;
    if (bid < 108)      { W = w0; Wt = t0; K = 192; N = 576; tn = bid % 18; tk = bid / 18; }
    else if (bid < 144) { bid -= 108; W = w1; Wt = t1; K = 192; N = 192; tn = bid % 6;  tk = bid / 6; }
    else if (bid < 288) { bid -= 144; W = w2; Wt = t2; K = 192; N = 768; tn = bid % 24; tk = bid / 24; }
    else                { bid -= 288; W = w3; Wt = t3; K = 768; N = 192; tn = bid % 6;  tk = bid / 6; }
    int k0 = tk * 32, n0 = tn * 32;
    int tx = threadIdx.x, ty = threadIdx.y;
#pragma unroll
    for (int i = 0; i < 32; i += 8)
        t[ty + i][tx] = W[(size_t)(k0 + ty + i) * N + n0 + tx];
    __syncthreads();
#pragma unroll
    for (int i = 0; i < 32; i += 8)
        Wt[(size_t)(n0 + ty + i) * K + k0 + tx] = __float2bfloat16(t[tx][ty + i]);
}

// ---------------------------------------------------------------------------
// K1: LayerNorm1 + roll(-3,-3) + window partition -> bf16 win
// ---------------------------------------------------------------------------
__global__ __launch_bounds__(256)
void ln1_win_kernel(const float* __restrict__ x,
                    const float* __restrict__ gam,
                    const float* __restrict__ bet,
                    bf16* __restrict__ win) {
    __shared__ float sm[32][193];
    int p0  = blockIdx.x * 32;
    int b   = p0 / PIX, yx0 = p0 % PIX;
    int tid = threadIdx.x, warp = tid >> 5, lane = tid & 31;

    const float* xb = x + (size_t)b * (DIM * PIX) + yx0;
#pragma unroll
    for (int cc = 0; cc < 24; ++cc) {
        int c = warp + cc * 8;
        sm[lane][c] = xb[(size_t)c * PIX + lane];
    }
    __syncthreads();

#pragma unroll
    for (int t = 0; t < 4; ++t) {
        int pix = warp * 4 + t;
        float v[6], s = 0.f, sq = 0.f;
#pragma unroll
        for (int j = 0; j < 6; ++j) {
            float u = sm[pix][lane + j * 32];
            v[j] = u; s += u; sq += u * u;
        }
#pragma unroll
        for (int o = 16; o; o >>= 1) {
            s  += __shfl_xor_sync(0xffffffffu, s,  o);
            sq += __shfl_xor_sync(0xffffffffu, sq, o);
        }
        float mu   = s * (1.f / DIM);
        float var  = sq * (1.f / DIM) - mu * mu;
        float rstd = rsqrtf(var + 1e-5f);

        int yx = yx0 + pix;
        int y  = yx / HW, xx = yx % HW;
        int y2 = (y  + HW - SHIFTV) % HW;
        int x2 = (xx + HW - SHIFTV) % HW;
        int r  = b * PIX + ((y2 / WS) * NW_GRID + (x2 / WS)) * NWIN
               + (y2 % WS) * WS + (x2 % WS);
        bf16* wp = win + (size_t)r * DIM;
#pragma unroll
        for (int j = 0; j < 6; ++j) {
            int c = lane + j * 32;
            wp[c] = __float2bfloat16((v[j] - mu) * rstd * gam[c] + bet[c]);
        }
    }
}

// ---------------------------------------------------------------------------
// K3: windowed attention. qkv in bf16 [row,576], output bf16 [row,192].
// ---------------------------------------------------------------------------
__global__ __launch_bounds__(128)
void attn_kernel(const bf16* __restrict__ qkv,
                 const float* __restrict__ rel_bias,
                 bf16* __restrict__ ao) {
    __shared__ float qs[NWIN * 33], ks[NWIN * 33], vs[NWIN * 33];
    __shared__ float prow[4][64];
    __shared__ int   cls[NWIN];

    int blk = blockIdx.x;
    int h = blk % HEADS, w = blk / HEADS;
    int widx = w & 63;
    int wi = widx >> 3, wj = widx & 7;
    int r0 = w * NWIN;
    int tid = threadIdx.x, warp = tid >> 5, lane = tid & 31;

    for (int e = tid; e < NWIN * HD; e += 128) {
        int t = e >> 5, d = e & 31;
        const bf16* base = qkv + (size_t)(r0 + t) * 576 + h * HD + d;
        qs[t * 33 + d] = __bfloat162float(base[0]) * SCALE_Q;
        ks[t * 33 + d] = __bfloat162float(base[192]);
        vs[t * 33 + d] = __bfloat162float(base[384]);
    }
    if (tid < NWIN) {
        int i = tid / WS, j = tid % WS;
        int ry = (wi < 7) ? 0 : ((i < WS - SHIFTV) ? 1 : 2);
        int rx = (wj < 7) ? 0 : ((j < WS - SHIFTV) ? 1 : 2);
        cls[tid] = ry * 3 + rx;
    }
    __syncthreads();

    for (int q = warp; q < NWIN; q += 4) {
        int c1 = lane;
        int c2 = lane + 32;
        bool has2 = (c2 < NWIN);
        int c2c = has2 ? c2 : (NWIN - 1);

        float s1 = 0.f, s2 = 0.f;
#pragma unroll
        for (int d = 0; d < HD; ++d) {
            float qv = qs[q * 33 + d];
            s1 += qv * ks[c1  * 33 + d];
            s2 += qv * ks[c2c * 33 + d];
        }
        int qi = q / WS, qj = q % WS;
        {
            int ki = c1 / WS, kj = c1 % WS;
            s1 += rel_bias[((qi - ki + 6) * 13 + (qj - kj + 6)) * HEADS + h];
            ki = c2c / WS; kj = c2c % WS;
            s2 += rel_bias[((qi - ki + 6) * 13 + (qj - kj + 6)) * HEADS + h];
        }
        int cq = cls[q];
        if (cls[c1] != cq) s1 = -1e30f;
        if (!has2 || cls[c2c] != cq) s2 = -1e30f;

        float mx = fmaxf(s1, s2);
#pragma unroll
        for (int o = 16; o; o >>= 1) mx = fmaxf(mx, __shfl_xor_sync(0xffffffffu, mx, o));
        float e1 = __expf(s1 - mx);
        float e2 = has2 ? __expf(s2 - mx) : 0.f;
        float sum = e1 + e2;
#pragma unroll
        for (int o = 16; o; o >>= 1) sum += __shfl_xor_sync(0xffffffffu, sum, o);
        float inv = 1.f / sum;

        prow[warp][lane]      = e1 * inv;
        prow[warp][lane + 32] = e2 * inv;
        __syncwarp();

        float acc = 0.f;
#pragma unroll
        for (int k = 0; k < NWIN; ++k) acc += prow[warp][k] * vs[k * 33 + lane];
        ao[(size_t)(r0 + q) * DIM + h * HD + lane] = __float2bfloat16(acc);
        __syncwarp();
    }
}

// ---------------------------------------------------------------------------
// K5: x1 = x + window-reverse(proj_out);  h2 = LN2(x1) -> bf16
// ---------------------------------------------------------------------------
__global__ __launch_bounds__(256)
void addln2_kernel(const float* __restrict__ x,
                   const float* __restrict__ po,
                   const float* __restrict__ gam,
                   const float* __restrict__ bet,
                   float* __restrict__ x1,
                   bf16* __restrict__ h2) {
    __shared__ float sm[32][193];
    int p0  = blockIdx.x * 32;
    int b   = p0 / PIX, yx0 = p0 % PIX;
    int tid = threadIdx.x, warp = tid >> 5, lane = tid & 31;

#pragma unroll
    for (int t = 0; t < 4; ++t) {
        int pix = warp * 4 + t;
        int yx = yx0 + pix;
        int y  = yx / HW, xx = yx % HW;
        int y2 = (y  + HW - SHIFTV) % HW;
        int x2 = (xx + HW - SHIFTV) % HW;
        int r  = b * PIX + ((y2 / WS) * NW_GRID + (x2 / WS)) * NWIN
               + (y2 % WS) * WS + (x2 % WS);
        const float* pp = po + (size_t)r * DIM;
#pragma unroll
        for (int j = 0; j < 6; ++j) {
            int c = lane + j * 32;
            sm[pix][c] = pp[c];
        }
    }
    __syncthreads();

    const float* xb = x  + (size_t)b * (DIM * PIX) + yx0;
    float*       xo = x1 + (size_t)b * (DIM * PIX) + yx0;
#pragma unroll
    for (int cc = 0; cc < 24; ++cc) {
        int c = warp + cc * 8;
        float v = xb[(size_t)c * PIX + lane] + sm[lane][c];
        xo[(size_t)c * PIX + lane] = v;
        sm[lane][c] = v;
    }
    __syncthreads();

#pragma unroll
    for (int t = 0; t < 4; ++t) {
        int pix = warp * 4 + t;
        float v[6], s = 0.f, sq = 0.f;
#pragma unroll
        for (int j = 0; j < 6; ++j) {
            float u = sm[pix][lane + j * 32];
            v[j] = u; s += u; sq += u * u;
        }
#pragma unroll
        for (int o = 16; o; o >>= 1) {
            s  += __shfl_xor_sync(0xffffffffu, s,  o);
            sq += __shfl_xor_sync(0xffffffffu, sq, o);
        }
        float mu   = s * (1.f / DIM);
        float var  = sq * (1.f / DIM) - mu * mu;
        float rstd = rsqrtf(var + 1e-5f);

        bf16* hp = h2 + (size_t)(p0 + pix) * DIM;
#pragma unroll
        for (int j = 0; j < 6; ++j) {
            int c = lane + j * 32;
            hp[c] = __float2bfloat16((v[j] - mu) * rstd * gam[c] + bet[c]);
        }
    }
}

// ---------------------------------------------------------------------------
// Launch
// ---------------------------------------------------------------------------
extern "C" void kernel_launch(void* const* d_in, const int* in_sizes, int n_in,
                              void* d_out, int out_size) {
    const float* x      = (const float*)d_in[0];
    const float* n1g    = (const float*)d_in[1];
    const float* n1b    = (const float*)d_in[2];
    const float* qkv_w  = (const float*)d_in[3];
    const float* qkv_b  = (const float*)d_in[4];
    const float* proj_w = (const float*)d_in[5];
    const float* proj_b = (const float*)d_in[6];
    const float* relb   = (const float*)d_in[7];
    const float* n2g    = (const float*)d_in[8];
    const float* n2b    = (const float*)d_in[9];
    const float* fc1_w  = (const float*)d_in[10];
    const float* fc1_b  = (const float*)d_in[11];
    const float* fc2_w  = (const float*)d_in[12];
    const float* fc2_b  = (const float*)d_in[13];
    float* out = (float*)d_out;

    bf16 *ba, *bb, *bg, *wqkv, *wproj, *wfc1, *wfc2;
    float *bpo, *bx1;
    cudaGetSymbolAddress((void**)&ba,   gb_a);
    cudaGetSymbolAddress((void**)&bb,   gb_b);
    cudaGetSymbolAddress((void**)&bg,   gb_big);
    cudaGetSymbolAddress((void**)&bpo,  g_projo);
    cudaGetSymbolAddress((void**)&bx1,  g_x1);
    cudaGetSymbolAddress((void**)&wqkv, g_qkv_wt);
    cudaGetSymbolAddress((void**)&wproj,g_proj_wt);
    cudaGetSymbolAddress((void**)&wfc1, g_fc1_wt);
    cudaGetSymbolAddress((void**)&wfc2, g_fc2_wt);

    // 0) all weight transposes + bf16 convert, one launch
    transpose_all<<<432, dim3(32, 8)>>>(qkv_w, proj_w, fc1_w, fc2_w,
                                        wqkv, wproj, wfc1, wfc2);

    // 1) LN1 + roll + window partition -> ba = win[50176,192] bf16
    ln1_win_kernel<<<NPIX / 32, 256>>>(x, n1g, n1b, ba);

    // 2) QKV GEMM -> bg[50176,576] bf16
    mma_gemm<2><<<dim3(576 / BN, NPIX / BM), 256>>>(ba, wqkv, qkv_b, bg,
                                                    nullptr, 576, 192);
    // 3) attention -> bb[50176,192] bf16
    attn_kernel<<<1024 * HEADS, 128>>>(bg, relb, bb);

    // 4) proj GEMM -> bpo fp32
    mma_gemm<0><<<dim3(192 / BN, NPIX / BM), 256>>>(bb, wproj, proj_b, bpo,
                                                    nullptr, 192, 192);
    // 5) residual + LN2 -> bx1 (NCHW fp32), ba = h2 bf16
    addln2_kernel<<<NPIX / 32, 256>>>(x, bpo, n2g, n2b, bx1, ba);

    // 6) fc1 + GELU -> bg[50176,768] bf16
    mma_gemm<1><<<dim3(768 / BN, NPIX / BM), 256>>>(ba, wfc1, fc1_b, bg,
                                                    nullptr, 768, 192);
    // 7) fc2 + fused residual -> out (NCHW fp32)
    mma_gemm<3><<<dim3(192 / BN, NPIX / BM), 256>>>(bg, wfc2, fc2_b, out,
                                                    bx1, 192, 768);
}

// round 9
// speedup vs baseline: 4.1251x; 1.5835x over previous
#include <cuda_runtime.h>
#include <cuda_bf16.h>
#include <math.h>
#include <stdint.h>

// ---------------------------------------------------------------------------
// Problem constants
// ---------------------------------------------------------------------------
#define BATCH   16
#define DIM     192
#define HW      56
#define PIX     3136            // 56*56
#define NPIX    50176           // 16*3136
#define WS      7
#define SHIFTV  3
#define NWIN    49
#define HEADS   6
#define HD      32
#define NW_GRID 8
#define SCALE_Q 0.1767766952966369f

typedef __nv_bfloat16 bf16;

// ---------------------------------------------------------------------------
// Scratch buffers (allocation-free: device globals)
// ---------------------------------------------------------------------------
__device__ __align__(128) bf16  gb_a   [NPIX * DIM];   // win (ln1 out) / h2 (ln2 out)
__device__ __align__(128) bf16  gb_b   [NPIX * DIM];   // attn out
__device__ __align__(128) bf16  gb_big [NPIX * 768];   // qkv out (576 used) / fc1 out
__device__ __align__(128) float g_projo[NPIX * DIM];   // proj out (fp32)
__device__ __align__(128) float g_x1   [NPIX * DIM];   // residual-1 (NCHW)
// transposed bf16 weights Wt[N][K]
__device__ __align__(128) bf16 g_qkv_wt [576 * 192];
__device__ __align__(128) bf16 g_proj_wt[192 * 192];
__device__ __align__(128) bf16 g_fc1_wt [768 * 192];
__device__ __align__(128) bf16 g_fc2_wt [192 * 768];
// precomputed attention bias+mask matrices: [head*4+cls][64][64] bf16
__device__ __align__(128) bf16 g_biasmat[24 * 64 * 64];

// ---------------------------------------------------------------------------
// PTX helpers
// ---------------------------------------------------------------------------
__device__ __forceinline__ void mma_bf16(float c[4], const uint32_t a[4],
                                         const uint32_t b0, const uint32_t b1) {
    asm volatile(
        "mma.sync.aligned.m16n8k16.row.col.f32.bf16.bf16.f32 "
        "{%0,%1,%2,%3}, {%4,%5,%6,%7}, {%8,%9}, {%0,%1,%2,%3};"
        : "+f"(c[0]), "+f"(c[1]), "+f"(c[2]), "+f"(c[3])
        : "r"(a[0]), "r"(a[1]), "r"(a[2]), "r"(a[3]),
          "r"(b0), "r"(b1));
}
__device__ __forceinline__ void ldsm4(uint32_t r[4], uint32_t addr) {
    asm volatile("ldmatrix.sync.aligned.m8n8.x4.shared.b16 {%0,%1,%2,%3}, [%4];"
                 : "=r"(r[0]), "=r"(r[1]), "=r"(r[2]), "=r"(r[3]) : "r"(addr));
}
__device__ __forceinline__ void ldsm4t(uint32_t r[4], uint32_t addr) {
    asm volatile("ldmatrix.sync.aligned.m8n8.x4.trans.shared.b16 {%0,%1,%2,%3}, [%4];"
                 : "=r"(r[0]), "=r"(r[1]), "=r"(r[2]), "=r"(r[3]) : "r"(addr));
}
__device__ __forceinline__ void cp16(uint32_t dst, const void* src) {
    asm volatile("cp.async.cg.shared.global [%0], [%1], 16;"
                 :: "r"(dst), "l"(src));
}
__device__ __forceinline__ void cp_commit() {
    asm volatile("cp.async.commit_group;" ::: "memory");
}
__device__ __forceinline__ void cp_wait0() {
    asm volatile("cp.async.wait_group 0;" ::: "memory");
}
__device__ __forceinline__ uint32_t sptr(const void* p) {
    return (uint32_t)__cvta_generic_to_shared(p);
}
__device__ __forceinline__ float bflo(uint32_t u) {
    return __uint_as_float(u << 16);
}
__device__ __forceinline__ float bfhi(uint32_t u) {
    return __uint_as_float(u & 0xffff0000u);
}
__device__ __forceinline__ uint32_t packbf(float a, float b) {
    __nv_bfloat162 t = __floats2bfloat162_rn(a, b);
    return *(uint32_t*)&t;
}

// ---------------------------------------------------------------------------
// bf16 tensor-core GEMM: C[M,Ntot] = A[M,K] @ Wt[N,K]^T + bias
// (unchanged from R7 — passing)
// MODE: 0 = fp32 out, 1 = bf16+GELU out, 2 = bf16 out,
//       3 = fp32 NCHW out with fused residual add (out = x1 + acc+bias).
// ---------------------------------------------------------------------------
#define BM 128
#define BN 96
#define BKC 32

template <int MODE>
__global__ __launch_bounds__(256, 2)
void mma_gemm(const bf16* __restrict__ A, const bf16* __restrict__ Bt,
              const float* __restrict__ bias, void* __restrict__ Cout,
              const float* __restrict__ x1aux, int Ntot, int K) {
    __shared__ __align__(16) char smA[2][BM * 64];
    __shared__ __align__(16) char smB[2][BN * 64];
    __shared__ float sbias[BN];

    int tid = threadIdx.x, lane = tid & 31, wid = tid >> 5;
    int wm = wid & 3, wn = wid >> 2;
    int m0 = blockIdx.y * BM;
    int n0 = blockIdx.x * BN;

    if (tid < BN) sbias[tid] = bias[n0 + tid];

    uint32_t aA[2] = { sptr(smA[0]), sptr(smA[1]) };
    uint32_t aB[2] = { sptr(smB[0]), sptr(smB[1]) };

    float acc[2][6][4];
#pragma unroll
    for (int i = 0; i < 2; ++i)
#pragma unroll
        for (int j = 0; j < 6; ++j)
#pragma unroll
            for (int l = 0; l < 4; ++l) acc[i][j][l] = 0.f;

    const int S = K / BKC;

    auto stage = [&](int kc, int buf) {
#pragma unroll
        for (int i = 0; i < 2; ++i) {
            int e = (i << 8) + tid;
            int row = e >> 2, g = e & 3;
            uint32_t dst = aA[buf] + row * 64 + ((g ^ ((row >> 1) & 3)) << 4);
            cp16(dst, A + (size_t)(m0 + row) * K + kc + g * 8);
        }
        {
            int row = tid >> 2, g = tid & 3;
            uint32_t dst = aB[buf] + row * 64 + ((g ^ ((row >> 1) & 3)) << 4);
            cp16(dst, Bt + (size_t)(n0 + row) * K + kc + g * 8);
        }
        if (tid < 128) {
            int e = 256 + tid;
            int row = e >> 2, g = e & 3;
            uint32_t dst = aB[buf] + row * 64 + ((g ^ ((row >> 1) & 3)) << 4);
            cp16(dst, Bt + (size_t)(n0 + row) * K + kc + g * 8);
        }
        cp_commit();
    };

    stage(0, 0);

    uint32_t aRow[2], aSw[2];
    int aHalf = lane >> 4;
#pragma unroll
    for (int tm = 0; tm < 2; ++tm) {
        int r = wm * 32 + tm * 16 + (lane & 15);
        aRow[tm] = r * 64;
        aSw[tm]  = (r >> 1) & 3;
    }
    uint32_t bRow[3], bSw[3];
    int bHalf = (lane >> 3) & 1;
#pragma unroll
    for (int p = 0; p < 3; ++p) {
        int r = wn * 48 + p * 16 + ((lane >> 4) << 3) + (lane & 7);
        bRow[p] = r * 64;
        bSw[p]  = (r >> 1) & 3;
    }

    for (int s = 0; s < S; ++s) {
        int buf = s & 1;
        cp_wait0();
        __syncthreads();
        if (s + 1 < S) stage((s + 1) * BKC, buf ^ 1);

        uint32_t bA = aA[buf], bB = aB[buf];
#pragma unroll
        for (int ks = 0; ks < 2; ++ks) {
            uint32_t af[2][4], bq[3][4];
#pragma unroll
            for (int tm = 0; tm < 2; ++tm)
                ldsm4(af[tm], bA + aRow[tm]
                      + ((((ks << 1) | aHalf) ^ aSw[tm]) << 4));
#pragma unroll
            for (int p = 0; p < 3; ++p)
                ldsm4(bq[p], bB + bRow[p]
                      + ((((ks << 1) | bHalf) ^ bSw[p]) << 4));
#pragma unroll
            for (int tm = 0; tm < 2; ++tm)
#pragma unroll
                for (int tn = 0; tn < 6; ++tn)
                    mma_bf16(acc[tm][tn], af[tm],
                             bq[tn >> 1][(tn & 1) << 1],
                             bq[tn >> 1][((tn & 1) << 1) + 1]);
        }
    }

    int q = lane & 3;
#pragma unroll
    for (int tm = 0; tm < 2; ++tm) {
        int r = m0 + wm * 32 + tm * 16 + (lane >> 2);
        size_t base1 = 0, base2 = 0;
        if (MODE == 3) {
            int b1 = r / PIX, yx1 = r % PIX;
            int r2 = r + 8;
            int b2 = r2 / PIX, yx2 = r2 % PIX;
            base1 = (size_t)b1 * (DIM * PIX) + yx1;
            base2 = (size_t)b2 * (DIM * PIX) + yx2;
        }
#pragma unroll
        for (int tn = 0; tn < 6; ++tn) {
            int cl = wn * 48 + tn * 8 + (q << 1);
            float b0 = sbias[cl], b1v = sbias[cl + 1];
            float v0 = acc[tm][tn][0] + b0;
            float v1 = acc[tm][tn][1] + b1v;
            float v2 = acc[tm][tn][2] + b0;
            float v3 = acc[tm][tn][3] + b1v;
            if (MODE == 1) {
                v0 = 0.5f * v0 * (1.f + erff(v0 * 0.70710678118654752f));
                v1 = 0.5f * v1 * (1.f + erff(v1 * 0.70710678118654752f));
                v2 = 0.5f * v2 * (1.f + erff(v2 * 0.70710678118654752f));
                v3 = 0.5f * v3 * (1.f + erff(v3 * 0.70710678118654752f));
            }
            if (MODE == 0) {
                float* C = (float*)Cout;
                *(float2*)(C + (size_t)r * Ntot + n0 + cl)       = make_float2(v0, v1);
                *(float2*)(C + (size_t)(r + 8) * Ntot + n0 + cl) = make_float2(v2, v3);
            } else if (MODE == 3) {
                float* O = (float*)Cout;
                size_t o00 = base1 + (size_t)(n0 + cl) * PIX;
                size_t o01 = base1 + (size_t)(n0 + cl + 1) * PIX;
                size_t o10 = base2 + (size_t)(n0 + cl) * PIX;
                size_t o11 = base2 + (size_t)(n0 + cl + 1) * PIX;
                O[o00] = x1aux[o00] + v0;
                O[o01] = x1aux[o01] + v1;
                O[o10] = x1aux[o10] + v2;
                O[o11] = x1aux[o11] + v3;
            } else {
                bf16* C = (bf16*)Cout;
                *(__nv_bfloat162*)(C + (size_t)r * Ntot + n0 + cl) =
                    __floats2bfloat162_rn(v0, v1);
                *(__nv_bfloat162*)(C + (size_t)(r + 8) * Ntot + n0 + cl) =
                    __floats2bfloat162_rn(v2, v3);
            }
        }
    }
}

// ---------------------------------------------------------------------------
// Bias matrices: [h*4+cls][q(64)][k(64)] = rel_bias + shift-mask, padded = -1e9
// cls bit1 = bottom-edge window (wi==7), bit0 = right-edge (wj==7)
// ---------------------------------------------------------------------------
__global__ void bias_build(const float* __restrict__ rel_bias,
                           bf16* __restrict__ bm) {
    int mat = blockIdx.x;            // 0..23
    int h = mat >> 2, cls = mat & 3;
    for (int e = threadIdx.x; e < 4096; e += 256) {
        int qq = e >> 6, kk = e & 63;
        float v = -1e9f;
        if (qq < NWIN && kk < NWIN) {
            int qi = qq / WS, qj = qq % WS, ki = kk / WS, kj = kk % WS;
            int ryq = (cls & 2) ? ((qi < WS - SHIFTV) ? 1 : 2) : 0;
            int rxq = (cls & 1) ? ((qj < WS - SHIFTV) ? 1 : 2) : 0;
            int ryk = (cls & 2) ? ((ki < WS - SHIFTV) ? 1 : 2) : 0;
            int rxk = (cls & 1) ? ((kj < WS - SHIFTV) ? 1 : 2) : 0;
            if (ryq == ryk && rxq == rxk)
                v = rel_bias[((qi - ki + 6) * 13 + (qj - kj + 6)) * HEADS + h];
        }
        bm[mat * 4096 + e] = __float2bfloat16(v);
    }
}

// ---------------------------------------------------------------------------
// K3: MMA windowed attention. Block = (window, head), 128 threads (4 warps).
// 49 tokens padded to 64. S = Q K^T (mma), +bias/mask (precomputed),
// softmax in fragments, O = P V (mma, V via ldmatrix.trans).
// ---------------------------------------------------------------------------
__global__ __launch_bounds__(128)
void attn_mma_kernel(const bf16* __restrict__ qkv,
                     const bf16* __restrict__ biasmat,
                     bf16* __restrict__ ao) {
    __shared__ __align__(16) bf16 sm[3 * 64 * 32];   // Q,K,V: 64 rows x 64B each

    int blk = blockIdx.x;
    int h = blk % HEADS, w = blk / HEADS;
    int widx = w & 63;
    int wi = widx >> 3, wj = widx & 7;
    int cls = ((wi == 7) ? 2 : 0) + ((wj == 7) ? 1 : 0);
    const bf16* bm = biasmat + (size_t)(h * 4 + cls) * 4096;
    int r0 = w * NWIN;
    int tid = threadIdx.x, lane = tid & 31, wid = tid >> 5;

    uint32_t sb = sptr(sm);

    // ---- load Q,K,V into swizzled smem (rows 49..63 zeroed) ----
    const uint4 z4 = make_uint4(0, 0, 0, 0);
    for (int e = tid; e < 768; e += 128) {
        int mat = e >> 8;               // 0=Q 1=K 2=V
        int rg  = e & 255;
        int row = rg >> 2, g = rg & 3;
        uint32_t dst = sb + mat * 4096 + row * 64 + ((g ^ ((row >> 1) & 3)) << 4);
        uint4 v = z4;
        if (row < NWIN)
            v = *(const uint4*)(qkv + (size_t)(r0 + row) * 576 + mat * 192
                                + h * HD + g * 8);
        *(uint4*)((char*)sm + (dst - sb)) = v;
    }
    __syncthreads();

    int qbase = wid * 16;
    int rw = lane & 7;

    // ---- S = Q K^T : M16 x N64 x K32 ----
    float sacc[8][4];
#pragma unroll
    for (int n = 0; n < 8; ++n)
#pragma unroll
        for (int l = 0; l < 4; ++l) sacc[n][l] = 0.f;

    // A addresses (same validated pattern as GEMM)
    int aHalf = lane >> 4;
    int arow = qbase + (lane & 15);
    uint32_t aAddrBase = sb + arow * 64;
    uint32_t aSw = (arow >> 1) & 3;
    // B addresses: row = t*16 + ((lane>>4)<<3) + (lane&7), g = 2c + ((lane>>3)&1)
    int bHalf = (lane >> 3) & 1;

#pragma unroll
    for (int c = 0; c < 2; ++c) {
        uint32_t af[4];
        ldsm4(af, aAddrBase + ((((c << 1) | aHalf) ^ aSw) << 4));
#pragma unroll
        for (int t = 0; t < 4; ++t) {
            int brow = t * 16 + ((lane >> 4) << 3) + rw;
            uint32_t bq[4];
            ldsm4(bq, sb + 4096 + brow * 64
                  + ((((c << 1) | bHalf) ^ ((brow >> 1) & 3)) << 4));
            mma_bf16(sacc[2 * t],     af, bq[0], bq[1]);
            mma_bf16(sacc[2 * t + 1], af, bq[2], bq[3]);
        }
    }

    // ---- scale + bias + softmax ----
    int rA = qbase + (lane >> 2);
    int rB = rA + 8;
    const bf16* bmA = bm + rA * 64 + ((lane & 3) << 1);
    const bf16* bmB = bm + rB * 64 + ((lane & 3) << 1);

    float mx0 = -1e30f, mx1 = -1e30f;
#pragma unroll
    for (int n = 0; n < 8; ++n) {
        uint32_t bb0 = *(const uint32_t*)(bmA + n * 8);
        uint32_t bb1 = *(const uint32_t*)(bmB + n * 8);
        sacc[n][0] = sacc[n][0] * SCALE_Q + bflo(bb0);
        sacc[n][1] = sacc[n][1] * SCALE_Q + bfhi(bb0);
        sacc[n][2] = sacc[n][2] * SCALE_Q + bflo(bb1);
        sacc[n][3] = sacc[n][3] * SCALE_Q + bfhi(bb1);
        mx0 = fmaxf(mx0, fmaxf(sacc[n][0], sacc[n][1]));
        mx1 = fmaxf(mx1, fmaxf(sacc[n][2], sacc[n][3]));
    }
    mx0 = fmaxf(mx0, __shfl_xor_sync(0xffffffffu, mx0, 1));
    mx0 = fmaxf(mx0, __shfl_xor_sync(0xffffffffu, mx0, 2));
    mx1 = fmaxf(mx1, __shfl_xor_sync(0xffffffffu, mx1, 1));
    mx1 = fmaxf(mx1, __shfl_xor_sync(0xffffffffu, mx1, 2));

    float sum0 = 0.f, sum1 = 0.f;
#pragma unroll
    for (int n = 0; n < 8; ++n) {
        sacc[n][0] = __expf(sacc[n][0] - mx0);
        sacc[n][1] = __expf(sacc[n][1] - mx0);
        sacc[n][2] = __expf(sacc[n][2] - mx1);
        sacc[n][3] = __expf(sacc[n][3] - mx1);
        sum0 += sacc[n][0] + sacc[n][1];
        sum1 += sacc[n][2] + sacc[n][3];
    }
    sum0 += __shfl_xor_sync(0xffffffffu, sum0, 1);
    sum0 += __shfl_xor_sync(0xffffffffu, sum0, 2);
    sum1 += __shfl_xor_sync(0xffffffffu, sum1, 1);
    sum1 += __shfl_xor_sync(0xffffffffu, sum1, 2);
    float inv0 = 1.f / sum0, inv1 = 1.f / sum1;

    uint32_t pA[8], pB[8];
#pragma unroll
    for (int n = 0; n < 8; ++n) {
        pA[n] = packbf(sacc[n][0] * inv0, sacc[n][1] * inv0);
        pB[n] = packbf(sacc[n][2] * inv1, sacc[n][3] * inv1);
    }

    // ---- O = P V : M16 x N32 x K64, V via ldmatrix.trans ----
    float oacc[4][4];
#pragma unroll
    for (int d = 0; d < 4; ++d)
#pragma unroll
        for (int l = 0; l < 4; ++l) oacc[d][l] = 0.f;

#pragma unroll
    for (int kc = 0; kc < 4; ++kc) {
        uint32_t af[4] = { pA[2 * kc], pB[2 * kc], pA[2 * kc + 1], pB[2 * kc + 1] };
        int vrow = kc * 16 + (((lane >> 3) & 1) << 3) + rw;
        uint32_t vswz = (vrow >> 1) & 3;
        int ghalf = (lane >> 4) & 1;
        uint32_t v01[4], v23[4];
        ldsm4t(v01, sb + 8192 + vrow * 64 + (((0 + ghalf) ^ vswz) << 4));
        ldsm4t(v23, sb + 8192 + vrow * 64 + (((2 + ghalf) ^ vswz) << 4));
        mma_bf16(oacc[0], af, v01[0], v01[1]);
        mma_bf16(oacc[1], af, v01[2], v01[3]);
        mma_bf16(oacc[2], af, v23[0], v23[1]);
        mma_bf16(oacc[3], af, v23[2], v23[3]);
    }

    // ---- store O rows < 49 ----
    int colb = h * HD + ((lane & 3) << 1);
    if (rA < NWIN) {
        bf16* op = ao + (size_t)(r0 + rA) * DIM + colb;
#pragma unroll
        for (int d = 0; d < 4; ++d)
            *(uint32_t*)(op + d * 8) = packbf(oacc[d][0], oacc[d][1]);
    }
    if (rB < NWIN) {
        bf16* op = ao + (size_t)(r0 + rB) * DIM + colb;
#pragma unroll
        for (int d = 0; d < 4; ++d)
            *(uint32_t*)(op + d * 8) = packbf(oacc[d][2], oacc[d][3]);
    }
}

// ---------------------------------------------------------------------------
// All 4 weight transposes (+bf16 convert) in ONE launch
// ---------------------------------------------------------------------------
__global__ void transpose_all(const float* __restrict__ w0, const float* __restrict__ w1,
                              const float* __restrict__ w2, const float* __restrict__ w3,
                              bf16* __restrict__ t0, bf16* __restrict__ t1,
                              bf16* __restrict__ t2, bf16* __restrict__ t3) {
    __shared__ float t[32][33];
    int bid = blockIdx.x;
    const float* W; bf16* Wt; int K, N, tn, tk;
    if (bid < 108)      { W = w0; Wt = t0; K = 192; N = 576; tn = bid % 18; tk = bid / 18; }
    else if (bid < 144) { bid -= 108; W = w1; Wt = t1; K = 192; N = 192; tn = bid % 6;  tk = bid / 6; }
    else if (bid < 288) { bid -= 144; W = w2; Wt = t2; K = 192; N = 768; tn = bid % 24; tk = bid / 24; }
    else                { bid -= 288; W = w3; Wt = t3; K = 768; N = 192; tn = bid % 6;  tk = bid / 6; }
    int k0 = tk * 32, n0 = tn * 32;
    int tx = threadIdx.x, ty = threadIdx.y;
#pragma unroll
    for (int i = 0; i < 32; i += 8)
        t[ty + i][tx] = W[(size_t)(k0 + ty + i) * N + n0 + tx];
    __syncthreads();
#pragma unroll
    for (int i = 0; i < 32; i += 8)
        Wt[(size_t)(n0 + ty + i) * K + k0 + tx] = __float2bfloat16(t[tx][ty + i]);
}

// ---------------------------------------------------------------------------
// K1: LayerNorm1 + roll(-3,-3) + window partition -> bf16 win
// ---------------------------------------------------------------------------
__global__ __launch_bounds__(256)
void ln1_win_kernel(const float* __restrict__ x,
                    const float* __restrict__ gam,
                    const float* __restrict__ bet,
                    bf16* __restrict__ win) {
    __shared__ float sm[32][193];
    int p0  = blockIdx.x * 32;
    int b   = p0 / PIX, yx0 = p0 % PIX;
    int tid = threadIdx.x, warp = tid >> 5, lane = tid & 31;

    const float* xb = x + (size_t)b * (DIM * PIX) + yx0;
#pragma unroll
    for (int cc = 0; cc < 24; ++cc) {
        int c = warp + cc * 8;
        sm[lane][c] = xb[(size_t)c * PIX + lane];
    }
    __syncthreads();

#pragma unroll
    for (int t = 0; t < 4; ++t) {
        int pix = warp * 4 + t;
        float v[6], s = 0.f, sq = 0.f;
#pragma unroll
        for (int j = 0; j < 6; ++j) {
            float u = sm[pix][lane + j * 32];
            v[j] = u; s += u; sq += u * u;
        }
#pragma unroll
        for (int o = 16; o; o >>= 1) {
            s  += __shfl_xor_sync(0xffffffffu, s,  o);
            sq += __shfl_xor_sync(0xffffffffu, sq, o);
        }
        float mu   = s * (1.f / DIM);
        float var  = sq * (1.f / DIM) - mu * mu;
        float rstd = rsqrtf(var + 1e-5f);

        int yx = yx0 + pix;
        int y  = yx / HW, xx = yx % HW;
        int y2 = (y  + HW - SHIFTV) % HW;
        int x2 = (xx + HW - SHIFTV) % HW;
        int r  = b * PIX + ((y2 / WS) * NW_GRID + (x2 / WS)) * NWIN
               + (y2 % WS) * WS + (x2 % WS);
        bf16* wp = win + (size_t)r * DIM;
#pragma unroll
        for (int j = 0; j < 6; ++j) {
            int c = lane + j * 32;
            wp[c] = __float2bfloat16((v[j] - mu) * rstd * gam[c] + bet[c]);
        }
    }
}

// ---------------------------------------------------------------------------
// K5: x1 = x + window-reverse(proj_out);  h2 = LN2(x1) -> bf16
// ---------------------------------------------------------------------------
__global__ __launch_bounds__(256)
void addln2_kernel(const float* __restrict__ x,
                   const float* __restrict__ po,
                   const float* __restrict__ gam,
                   const float* __restrict__ bet,
                   float* __restrict__ x1,
                   bf16* __restrict__ h2) {
    __shared__ float sm[32][193];
    int p0  = blockIdx.x * 32;
    int b   = p0 / PIX, yx0 = p0 % PIX;
    int tid = threadIdx.x, warp = tid >> 5, lane = tid & 31;

#pragma unroll
    for (int t = 0; t < 4; ++t) {
        int pix = warp * 4 + t;
        int yx = yx0 + pix;
        int y  = yx / HW, xx = yx % HW;
        int y2 = (y  + HW - SHIFTV) % HW;
        int x2 = (xx + HW - SHIFTV) % HW;
        int r  = b * PIX + ((y2 / WS) * NW_GRID + (x2 / WS)) * NWIN
               + (y2 % WS) * WS + (x2 % WS);
        const float* pp = po + (size_t)r * DIM;
#pragma unroll
        for (int j = 0; j < 6; ++j) {
            int c = lane + j * 32;
            sm[pix][c] = pp[c];
        }
    }
    __syncthreads();

    const float* xb = x  + (size_t)b * (DIM * PIX) + yx0;
    float*       xo = x1 + (size_t)b * (DIM * PIX) + yx0;
#pragma unroll
    for (int cc = 0; cc < 24; ++cc) {
        int c = warp + cc * 8;
        float v = xb[(size_t)c * PIX + lane] + sm[lane][c];
        xo[(size_t)c * PIX + lane] = v;
        sm[lane][c] = v;
    }
    __syncthreads();

#pragma unroll
    for (int t = 0; t < 4; ++t) {
        int pix = warp * 4 + t;
        float v[6], s = 0.f, sq = 0.f;
#pragma unroll
        for (int j = 0; j < 6; ++j) {
            float u = sm[pix][lane + j * 32];
            v[j] = u; s += u; sq += u * u;
        }
#pragma unroll
        for (int o = 16; o; o >>= 1) {
            s  += __shfl_xor_sync(0xffffffffu, s,  o);
            sq += __shfl_xor_sync(0xffffffffu, sq, o);
        }
        float mu   = s * (1.f / DIM);
        float var  = sq * (1.f / DIM) - mu * mu;
        float rstd = rsqrtf(var + 1e-5f);

        bf16* hp = h2 + (size_t)(p0 + pix) * DIM;
#pragma unroll
        for (int j = 0; j < 6; ++j) {
            int c = lane + j * 32;
            hp[c] = __float2bfloat16((v[j] - mu) * rstd * gam[c] + bet[c]);
        }
    }
}

// ---------------------------------------------------------------------------
// Launch
// ---------------------------------------------------------------------------
extern "C" void kernel_launch(void* const* d_in, const int* in_sizes, int n_in,
                              void* d_out, int out_size) {
    const float* x      = (const float*)d_in[0];
    const float* n1g    = (const float*)d_in[1];
    const float* n1b    = (const float*)d_in[2];
    const float* qkv_w  = (const float*)d_in[3];
    const float* qkv_b  = (const float*)d_in[4];
    const float* proj_w = (const float*)d_in[5];
    const float* proj_b = (const float*)d_in[6];
    const float* relb   = (const float*)d_in[7];
    const float* n2g    = (const float*)d_in[8];
    const float* n2b    = (const float*)d_in[9];
    const float* fc1_w  = (const float*)d_in[10];
    const float* fc1_b  = (const float*)d_in[11];
    const float* fc2_w  = (const float*)d_in[12];
    const float* fc2_b  = (const float*)d_in[13];
    float* out = (float*)d_out;

    bf16 *ba, *bb, *bg, *wqkv, *wproj, *wfc1, *wfc2, *bmat;
    float *bpo, *bx1;
    cudaGetSymbolAddress((void**)&ba,   gb_a);
    cudaGetSymbolAddress((void**)&bb,   gb_b);
    cudaGetSymbolAddress((void**)&bg,   gb_big);
    cudaGetSymbolAddress((void**)&bpo,  g_projo);
    cudaGetSymbolAddress((void**)&bx1,  g_x1);
    cudaGetSymbolAddress((void**)&wqkv, g_qkv_wt);
    cudaGetSymbolAddress((void**)&wproj,g_proj_wt);
    cudaGetSymbolAddress((void**)&wfc1, g_fc1_wt);
    cudaGetSymbolAddress((void**)&wfc2, g_fc2_wt);
    cudaGetSymbolAddress((void**)&bmat, g_biasmat);

    // 0) weight transposes + bias/mask matrices
    transpose_all<<<432, dim3(32, 8)>>>(qkv_w, proj_w, fc1_w, fc2_w,
                                        wqkv, wproj, wfc1, wfc2);
    bias_build<<<24, 256>>>(relb, bmat);

    // 1) LN1 + roll + window partition -> ba = win[50176,192] bf16
    ln1_win_kernel<<<NPIX / 32, 256>>>(x, n1g, n1b, ba);

    // 2) QKV GEMM -> bg[50176,576] bf16
    mma_gemm<2><<<dim3(576 / BN, NPIX / BM), 256>>>(ba, wqkv, qkv_b, bg,
                                                    nullptr, 576, 192);
    // 3) MMA attention -> bb[50176,192] bf16
    attn_mma_kernel<<<1024 * HEADS, 128>>>(bg, bmat, bb);

    // 4) proj GEMM -> bpo fp32
    mma_gemm<0><<<dim3(192 / BN, NPIX / BM), 256>>>(bb, wproj, proj_b, bpo,
                                                    nullptr, 192, 192);
    // 5) residual + LN2 -> bx1 (NCHW fp32), ba = h2 bf16
    addln2_kernel<<<NPIX / 32, 256>>>(x, bpo, n2g, n2b, bx1, ba);

    // 6) fc1 + GELU -> bg[50176,768] bf16
    mma_gemm<1><<<dim3(768 / BN, NPIX / BM), 256>>>(ba, wfc1, fc1_b, bg,
                                                    nullptr, 768, 192);
    // 7) fc2 + fused residual -> out (NCHW fp32)
    mma_gemm<3><<<dim3(192 / BN, NPIX / BM), 256>>>(bg, wfc2, fc2_b, out,
                                                    bx1, 192, 768);
}

// round 10
// speedup vs baseline: 4.1995x; 1.0180x over previous
#include <cuda_runtime.h>
#include <cuda_bf16.h>
#include <math.h>
#include <stdint.h>

// ---------------------------------------------------------------------------
// Problem constants
// ---------------------------------------------------------------------------
#define BATCH   16
#define DIM     192
#define HW      56
#define PIX     3136            // 56*56
#define NPIX    50176           // 16*3136
#define WS      7
#define SHIFTV  3
#define NWIN    49
#define HEADS   6
#define HD      32
#define NW_GRID 8
#define SCALE_Q 0.1767766952966369f

typedef __nv_bfloat16 bf16;

// ---------------------------------------------------------------------------
// Scratch buffers (allocation-free: device globals)
// ---------------------------------------------------------------------------
__device__ __align__(128) bf16  gb_a   [NPIX * DIM];   // win (ln1 out) / h2 (ln2 out)
__device__ __align__(128) bf16  gb_b   [NPIX * DIM];   // attn out
__device__ __align__(128) bf16  gb_big [NPIX * 768];   // qkv out (576 used) / fc1 out
__device__ __align__(128) float g_projo[NPIX * DIM];   // proj out (fp32)
__device__ __align__(128) float g_x1   [NPIX * DIM];   // residual-1 (NCHW)
// transposed bf16 weights Wt[N][K]
__device__ __align__(128) bf16 g_qkv_wt [576 * 192];
__device__ __align__(128) bf16 g_proj_wt[192 * 192];
__device__ __align__(128) bf16 g_fc1_wt [768 * 192];
__device__ __align__(128) bf16 g_fc2_wt [192 * 768];
// precomputed attention bias+mask matrices: [head*4+cls][64][64] bf16
__device__ __align__(128) bf16 g_biasmat[24 * 64 * 64];

// ---------------------------------------------------------------------------
// PTX helpers
// ---------------------------------------------------------------------------
__device__ __forceinline__ void mma_bf16(float c[4], const uint32_t a[4],
                                         const uint32_t b0, const uint32_t b1) {
    asm volatile(
        "mma.sync.aligned.m16n8k16.row.col.f32.bf16.bf16.f32 "
        "{%0,%1,%2,%3}, {%4,%5,%6,%7}, {%8,%9}, {%0,%1,%2,%3};"
        : "+f"(c[0]), "+f"(c[1]), "+f"(c[2]), "+f"(c[3])
        : "r"(a[0]), "r"(a[1]), "r"(a[2]), "r"(a[3]),
          "r"(b0), "r"(b1));
}
__device__ __forceinline__ void ldsm4(uint32_t r[4], uint32_t addr) {
    asm volatile("ldmatrix.sync.aligned.m8n8.x4.shared.b16 {%0,%1,%2,%3}, [%4];"
                 : "=r"(r[0]), "=r"(r[1]), "=r"(r[2]), "=r"(r[3]) : "r"(addr));
}
__device__ __forceinline__ void ldsm4t(uint32_t r[4], uint32_t addr) {
    asm volatile("ldmatrix.sync.aligned.m8n8.x4.trans.shared.b16 {%0,%1,%2,%3}, [%4];"
                 : "=r"(r[0]), "=r"(r[1]), "=r"(r[2]), "=r"(r[3]) : "r"(addr));
}
__device__ __forceinline__ void cp16(uint32_t dst, const void* src) {
    asm volatile("cp.async.cg.shared.global [%0], [%1], 16;"
                 :: "r"(dst), "l"(src));
}
__device__ __forceinline__ void cp_commit() {
    asm volatile("cp.async.commit_group;" ::: "memory");
}
template <int N>
__device__ __forceinline__ void cp_wait() {
    asm volatile("cp.async.wait_group %0;" :: "n"(N) : "memory");
}
__device__ __forceinline__ uint32_t sptr(const void* p) {
    return (uint32_t)__cvta_generic_to_shared(p);
}
__device__ __forceinline__ float bflo(uint32_t u) {
    return __uint_as_float(u << 16);
}
__device__ __forceinline__ float bfhi(uint32_t u) {
    return __uint_as_float(u & 0xffff0000u);
}
__device__ __forceinline__ uint32_t packbf(float a, float b) {
    __nv_bfloat162 t = __floats2bfloat162_rn(a, b);
    return *(uint32_t*)&t;
}

// ---------------------------------------------------------------------------
// bf16 tensor-core GEMM: C[M,Ntot] = A[M,K] @ Wt[N,K]^T + bias
// BM=128, BN=96, BKC=32; 256 threads = 8 warps (4 M x 2 N), warp tile 32x48.
// 3-stage cp.async pipeline: two stage-loads in flight (wait_group 1)
// so DRAM latency is covered by two stages of compute.
// MODE: 0 = fp32 out, 1 = bf16+GELU out, 2 = bf16 out,
//       3 = fp32 NCHW out with fused residual add (out = x1 + acc+bias).
// ---------------------------------------------------------------------------
#define BM 128
#define BN 96
#define BKC 32
#define NSTAGE 3

template <int MODE>
__global__ __launch_bounds__(256, 2)
void mma_gemm(const bf16* __restrict__ A, const bf16* __restrict__ Bt,
              const float* __restrict__ bias, void* __restrict__ Cout,
              const float* __restrict__ x1aux, int Ntot, int K) {
    __shared__ __align__(16) char smA[NSTAGE][BM * 64];
    __shared__ __align__(16) char smB[NSTAGE][BN * 64];
    __shared__ float sbias[BN];

    int tid = threadIdx.x, lane = tid & 31, wid = tid >> 5;
    int wm = wid & 3, wn = wid >> 2;
    int m0 = blockIdx.y * BM;
    int n0 = blockIdx.x * BN;

    if (tid < BN) sbias[tid] = bias[n0 + tid];

    uint32_t aA[NSTAGE], aB[NSTAGE];
#pragma unroll
    for (int i = 0; i < NSTAGE; ++i) {
        aA[i] = sptr(smA[i]);
        aB[i] = sptr(smB[i]);
    }

    float acc[2][6][4];
#pragma unroll
    for (int i = 0; i < 2; ++i)
#pragma unroll
        for (int j = 0; j < 6; ++j)
#pragma unroll
            for (int l = 0; l < 4; ++l) acc[i][j][l] = 0.f;

    const int S = K / BKC;     // >= 6 always

    auto stage = [&](int kc, int buf) {
#pragma unroll
        for (int i = 0; i < 2; ++i) {          // A: 512 16B-groups
            int e = (i << 8) + tid;
            int row = e >> 2, g = e & 3;
            uint32_t dst = aA[buf] + row * 64 + ((g ^ ((row >> 1) & 3)) << 4);
            cp16(dst, A + (size_t)(m0 + row) * K + kc + g * 8);
        }
        {                                       // B: 384 16B-groups
            int row = tid >> 2, g = tid & 3;
            uint32_t dst = aB[buf] + row * 64 + ((g ^ ((row >> 1) & 3)) << 4);
            cp16(dst, Bt + (size_t)(n0 + row) * K + kc + g * 8);
        }
        if (tid < 128) {
            int e = 256 + tid;
            int row = e >> 2, g = e & 3;
            uint32_t dst = aB[buf] + row * 64 + ((g ^ ((row >> 1) & 3)) << 4);
            cp16(dst, Bt + (size_t)(n0 + row) * K + kc + g * 8);
        }
        cp_commit();
    };

    // ldmatrix per-lane address components (validated pattern)
    uint32_t aRow[2], aSw[2];
    int aHalf = lane >> 4;
#pragma unroll
    for (int tm = 0; tm < 2; ++tm) {
        int r = wm * 32 + tm * 16 + (lane & 15);
        aRow[tm] = r * 64;
        aSw[tm]  = (r >> 1) & 3;
    }
    uint32_t bRow[3], bSw[3];
    int bHalf = (lane >> 3) & 1;
#pragma unroll
    for (int p = 0; p < 3; ++p) {
        int r = wn * 48 + p * 16 + ((lane >> 4) << 3) + (lane & 7);
        bRow[p] = r * 64;
        bSw[p]  = (r >> 1) & 3;
    }

    auto compute = [&](int buf) {
        uint32_t bA = aA[buf], bB = aB[buf];
#pragma unroll
        for (int ks = 0; ks < 2; ++ks) {
            uint32_t af[2][4], bq[3][4];
#pragma unroll
            for (int tm = 0; tm < 2; ++tm)
                ldsm4(af[tm], bA + aRow[tm]
                      + ((((ks << 1) | aHalf) ^ aSw[tm]) << 4));
#pragma unroll
            for (int p = 0; p < 3; ++p)
                ldsm4(bq[p], bB + bRow[p]
                      + ((((ks << 1) | bHalf) ^ bSw[p]) << 4));
#pragma unroll
            for (int tm = 0; tm < 2; ++tm)
#pragma unroll
                for (int tn = 0; tn < 6; ++tn)
                    mma_bf16(acc[tm][tn], af[tm],
                             bq[tn >> 1][(tn & 1) << 1],
                             bq[tn >> 1][((tn & 1) << 1) + 1]);
        }
    };

    // prologue: 2 stages in flight
    stage(0, 0);
    stage(BKC, 1);

    int buf = 0;
    for (int s = 0; s < S - 1; ++s) {
        cp_wait<1>();                 // stage s complete (s+1 still in flight)
        __syncthreads();
        if (s + 2 < S) stage((s + 2) * BKC, (buf + 2) % NSTAGE);
        compute(buf);
        buf = (buf + 1) % NSTAGE;
    }
    cp_wait<0>();                     // last stage complete
    __syncthreads();
    compute(buf);

    // ---- epilogue ----
    int q = lane & 3;
#pragma unroll
    for (int tm = 0; tm < 2; ++tm) {
        int r = m0 + wm * 32 + tm * 16 + (lane >> 2);
        size_t base1 = 0, base2 = 0;
        if (MODE == 3) {
            int b1 = r / PIX, yx1 = r % PIX;
            int r2 = r + 8;
            int b2 = r2 / PIX, yx2 = r2 % PIX;
            base1 = (size_t)b1 * (DIM * PIX) + yx1;
            base2 = (size_t)b2 * (DIM * PIX) + yx2;
        }
#pragma unroll
        for (int tn = 0; tn < 6; ++tn) {
            int cl = wn * 48 + tn * 8 + (q << 1);
            float b0 = sbias[cl], b1v = sbias[cl + 1];
            float v0 = acc[tm][tn][0] + b0;
            float v1 = acc[tm][tn][1] + b1v;
            float v2 = acc[tm][tn][2] + b0;
            float v3 = acc[tm][tn][3] + b1v;
            if (MODE == 1) {
                v0 = 0.5f * v0 * (1.f + erff(v0 * 0.70710678118654752f));
                v1 = 0.5f * v1 * (1.f + erff(v1 * 0.70710678118654752f));
                v2 = 0.5f * v2 * (1.f + erff(v2 * 0.70710678118654752f));
                v3 = 0.5f * v3 * (1.f + erff(v3 * 0.70710678118654752f));
            }
            if (MODE == 0) {
                float* C = (float*)Cout;
                *(float2*)(C + (size_t)r * Ntot + n0 + cl)       = make_float2(v0, v1);
                *(float2*)(C + (size_t)(r + 8) * Ntot + n0 + cl) = make_float2(v2, v3);
            } else if (MODE == 3) {
                float* O = (float*)Cout;
                size_t o00 = base1 + (size_t)(n0 + cl) * PIX;
                size_t o01 = base1 + (size_t)(n0 + cl + 1) * PIX;
                size_t o10 = base2 + (size_t)(n0 + cl) * PIX;
                size_t o11 = base2 + (size_t)(n0 + cl + 1) * PIX;
                O[o00] = x1aux[o00] + v0;
                O[o01] = x1aux[o01] + v1;
                O[o10] = x1aux[o10] + v2;
                O[o11] = x1aux[o11] + v3;
            } else {
                bf16* C = (bf16*)Cout;
                *(__nv_bfloat162*)(C + (size_t)r * Ntot + n0 + cl) =
                    __floats2bfloat162_rn(v0, v1);
                *(__nv_bfloat162*)(C + (size_t)(r + 8) * Ntot + n0 + cl) =
                    __floats2bfloat162_rn(v2, v3);
            }
        }
    }
}

// ---------------------------------------------------------------------------
// Bias matrices: [h*4+cls][q(64)][k(64)] = rel_bias + shift-mask, padded = -1e9
// ---------------------------------------------------------------------------
__global__ void bias_build(const float* __restrict__ rel_bias,
                           bf16* __restrict__ bm) {
    int mat = blockIdx.x;            // 0..23
    int h = mat >> 2, cls = mat & 3;
    for (int e = threadIdx.x; e < 4096; e += 256) {
        int qq = e >> 6, kk = e & 63;
        float v = -1e9f;
        if (qq < NWIN && kk < NWIN) {
            int qi = qq / WS, qj = qq % WS, ki = kk / WS, kj = kk % WS;
            int ryq = (cls & 2) ? ((qi < WS - SHIFTV) ? 1 : 2) : 0;
            int rxq = (cls & 1) ? ((qj < WS - SHIFTV) ? 1 : 2) : 0;
            int ryk = (cls & 2) ? ((ki < WS - SHIFTV) ? 1 : 2) : 0;
            int rxk = (cls & 1) ? ((kj < WS - SHIFTV) ? 1 : 2) : 0;
            if (ryq == ryk && rxq == rxk)
                v = rel_bias[((qi - ki + 6) * 13 + (qj - kj + 6)) * HEADS + h];
        }
        bm[mat * 4096 + e] = __float2bfloat16(v);
    }
}

// ---------------------------------------------------------------------------
// K3: MMA windowed attention (unchanged from R8 — passing)
// ---------------------------------------------------------------------------
__global__ __launch_bounds__(128)
void attn_mma_kernel(const bf16* __restrict__ qkv,
                     const bf16* __restrict__ biasmat,
                     bf16* __restrict__ ao) {
    __shared__ __align__(16) bf16 sm[3 * 64 * 32];   // Q,K,V: 64 rows x 64B each

    int blk = blockIdx.x;
    int h = blk % HEADS, w = blk / HEADS;
    int widx = w & 63;
    int wi = widx >> 3, wj = widx & 7;
    int cls = ((wi == 7) ? 2 : 0) + ((wj == 7) ? 1 : 0);
    const bf16* bm = biasmat + (size_t)(h * 4 + cls) * 4096;
    int r0 = w * NWIN;
    int tid = threadIdx.x, lane = tid & 31, wid = tid >> 5;

    uint32_t sb = sptr(sm);

    const uint4 z4 = make_uint4(0, 0, 0, 0);
    for (int e = tid; e < 768; e += 128) {
        int mat = e >> 8;               // 0=Q 1=K 2=V
        int rg  = e & 255;
        int row = rg >> 2, g = rg & 3;
        uint32_t dst = sb + mat * 4096 + row * 64 + ((g ^ ((row >> 1) & 3)) << 4);
        uint4 v = z4;
        if (row < NWIN)
            v = *(const uint4*)(qkv + (size_t)(r0 + row) * 576 + mat * 192
                                + h * HD + g * 8);
        *(uint4*)((char*)sm + (dst - sb)) = v;
    }
    __syncthreads();

    int qbase = wid * 16;
    int rw = lane & 7;

    float sacc[8][4];
#pragma unroll
    for (int n = 0; n < 8; ++n)
#pragma unroll
        for (int l = 0; l < 4; ++l) sacc[n][l] = 0.f;

    int aHalf = lane >> 4;
    int arow = qbase + (lane & 15);
    uint32_t aAddrBase = sb + arow * 64;
    uint32_t aSw = (arow >> 1) & 3;
    int bHalf = (lane >> 3) & 1;

#pragma unroll
    for (int c = 0; c < 2; ++c) {
        uint32_t af[4];
        ldsm4(af, aAddrBase + ((((c << 1) | aHalf) ^ aSw) << 4));
#pragma unroll
        for (int t = 0; t < 4; ++t) {
            int brow = t * 16 + ((lane >> 4) << 3) + rw;
            uint32_t bq[4];
            ldsm4(bq, sb + 4096 + brow * 64
                  + ((((c << 1) | bHalf) ^ ((brow >> 1) & 3)) << 4));
            mma_bf16(sacc[2 * t],     af, bq[0], bq[1]);
            mma_bf16(sacc[2 * t + 1], af, bq[2], bq[3]);
        }
    }

    int rA = qbase + (lane >> 2);
    int rB = rA + 8;
    const bf16* bmA = bm + rA * 64 + ((lane & 3) << 1);
    const bf16* bmB = bm + rB * 64 + ((lane & 3) << 1);

    float mx0 = -1e30f, mx1 = -1e30f;
#pragma unroll
    for (int n = 0; n < 8; ++n) {
        uint32_t bb0 = *(const uint32_t*)(bmA + n * 8);
        uint32_t bb1 = *(const uint32_t*)(bmB + n * 8);
        sacc[n][0] = sacc[n][0] * SCALE_Q + bflo(bb0);
        sacc[n][1] = sacc[n][1] * SCALE_Q + bfhi(bb0);
        sacc[n][2] = sacc[n][2] * SCALE_Q + bflo(bb1);
        sacc[n][3] = sacc[n][3] * SCALE_Q + bfhi(bb1);
        mx0 = fmaxf(mx0, fmaxf(sacc[n][0], sacc[n][1]));
        mx1 = fmaxf(mx1, fmaxf(sacc[n][2], sacc[n][3]));
    }
    mx0 = fmaxf(mx0, __shfl_xor_sync(0xffffffffu, mx0, 1));
    mx0 = fmaxf(mx0, __shfl_xor_sync(0xffffffffu, mx0, 2));
    mx1 = fmaxf(mx1, __shfl_xor_sync(0xffffffffu, mx1, 1));
    mx1 = fmaxf(mx1, __shfl_xor_sync(0xffffffffu, mx1, 2));

    float sum0 = 0.f, sum1 = 0.f;
#pragma unroll
    for (int n = 0; n < 8; ++n) {
        sacc[n][0] = __expf(sacc[n][0] - mx0);
        sacc[n][1] = __expf(sacc[n][1] - mx0);
        sacc[n][2] = __expf(sacc[n][2] - mx1);
        sacc[n][3] = __expf(sacc[n][3] - mx1);
        sum0 += sacc[n][0] + sacc[n][1];
        sum1 += sacc[n][2] + sacc[n][3];
    }
    sum0 += __shfl_xor_sync(0xffffffffu, sum0, 1);
    sum0 += __shfl_xor_sync(0xffffffffu, sum0, 2);
    sum1 += __shfl_xor_sync(0xffffffffu, sum1, 1);
    sum1 += __shfl_xor_sync(0xffffffffu, sum1, 2);
    float inv0 = 1.f / sum0, inv1 = 1.f / sum1;

    uint32_t pA[8], pB[8];
#pragma unroll
    for (int n = 0; n < 8; ++n) {
        pA[n] = packbf(sacc[n][0] * inv0, sacc[n][1] * inv0);
        pB[n] = packbf(sacc[n][2] * inv1, sacc[n][3] * inv1);
    }

    float oacc[4][4];
#pragma unroll
    for (int d = 0; d < 4; ++d)
#pragma unroll
        for (int l = 0; l < 4; ++l) oacc[d][l] = 0.f;

#pragma unroll
    for (int kc = 0; kc < 4; ++kc) {
        uint32_t af[4] = { pA[2 * kc], pB[2 * kc], pA[2 * kc + 1], pB[2 * kc + 1] };
        int vrow = kc * 16 + (((lane >> 3) & 1) << 3) + rw;
        uint32_t vswz = (vrow >> 1) & 3;
        int ghalf = (lane >> 4) & 1;
        uint32_t v01[4], v23[4];
        ldsm4t(v01, sb + 8192 + vrow * 64 + (((0 + ghalf) ^ vswz) << 4));
        ldsm4t(v23, sb + 8192 + vrow * 64 + (((2 + ghalf) ^ vswz) << 4));
        mma_bf16(oacc[0], af, v01[0], v01[1]);
        mma_bf16(oacc[1], af, v01[2], v01[3]);
        mma_bf16(oacc[2], af, v23[0], v23[1]);
        mma_bf16(oacc[3], af, v23[2], v23[3]);
    }

    int colb = h * HD + ((lane & 3) << 1);
    if (rA < NWIN) {
        bf16* op = ao + (size_t)(r0 + rA) * DIM + colb;
#pragma unroll
        for (int d = 0; d < 4; ++d)
            *(uint32_t*)(op + d * 8) = packbf(oacc[d][0], oacc[d][1]);
    }
    if (rB < NWIN) {
        bf16* op = ao + (size_t)(r0 + rB) * DIM + colb;
#pragma unroll
        for (int d = 0; d < 4; ++d)
            *(uint32_t*)(op + d * 8) = packbf(oacc[d][2], oacc[d][3]);
    }
}

// ---------------------------------------------------------------------------
// All 4 weight transposes (+bf16 convert) in ONE launch
// ---------------------------------------------------------------------------
__global__ void transpose_all(const float* __restrict__ w0, const float* __restrict__ w1,
                              const float* __restrict__ w2, const float* __restrict__ w3,
                              bf16* __restrict__ t0, bf16* __restrict__ t1,
                              bf16* __restrict__ t2, bf16* __restrict__ t3) {
    __shared__ float t[32][33];
    int bid = blockIdx.x;
    const float* W; bf16* Wt; int K, N, tn, tk;
    if (bid < 108)      { W = w0; Wt = t0; K = 192; N = 576; tn = bid % 18; tk = bid / 18; }
    else if (bid < 144) { bid -= 108; W = w1; Wt = t1; K = 192; N = 192; tn = bid % 6;  tk = bid / 6; }
    else if (bid < 288) { bid -= 144; W = w2; Wt = t2; K = 192; N = 768; tn = bid % 24; tk = bid / 24; }
    else                { bid -= 288; W = w3; Wt = t3; K = 768; N = 192; tn = bid % 6;  tk = bid / 6; }
    int k0 = tk * 32, n0 = tn * 32;
    int tx = threadIdx.x, ty = threadIdx.y;
#pragma unroll
    for (int i = 0; i < 32; i += 8)
        t[ty + i][tx] = W[(size_t)(k0 + ty + i) * N + n0 + tx];
    __syncthreads();
#pragma unroll
    for (int i = 0; i < 32; i += 8)
        Wt[(size_t)(n0 + ty + i) * K + k0 + tx] = __float2bfloat16(t[tx][ty + i]);
}

// ---------------------------------------------------------------------------
// K1: LayerNorm1 + roll(-3,-3) + window partition -> bf16 win
// ---------------------------------------------------------------------------
__global__ __launch_bounds__(256)
void ln1_win_kernel(const float* __restrict__ x,
                    const float* __restrict__ gam,
                    const float* __restrict__ bet,
                    bf16* __restrict__ win) {
    __shared__ float sm[32][193];
    int p0  = blockIdx.x * 32;
    int b   = p0 / PIX, yx0 = p0 % PIX;
    int tid = threadIdx.x, warp = tid >> 5, lane = tid & 31;

    const float* xb = x + (size_t)b * (DIM * PIX) + yx0;
#pragma unroll
    for (int cc = 0; cc < 24; ++cc) {
        int c = warp + cc * 8;
        sm[lane][c] = xb[(size_t)c * PIX + lane];
    }
    __syncthreads();

#pragma unroll
    for (int t = 0; t < 4; ++t) {
        int pix = warp * 4 + t;
        float v[6], s = 0.f, sq = 0.f;
#pragma unroll
        for (int j = 0; j < 6; ++j) {
            float u = sm[pix][lane + j * 32];
            v[j] = u; s += u; sq += u * u;
        }
#pragma unroll
        for (int o = 16; o; o >>= 1) {
            s  += __shfl_xor_sync(0xffffffffu, s,  o);
            sq += __shfl_xor_sync(0xffffffffu, sq, o);
        }
        float mu   = s * (1.f / DIM);
        float var  = sq * (1.f / DIM) - mu * mu;
        float rstd = rsqrtf(var + 1e-5f);

        int yx = yx0 + pix;
        int y  = yx / HW, xx = yx % HW;
        int y2 = (y  + HW - SHIFTV) % HW;
        int x2 = (xx + HW - SHIFTV) % HW;
        int r  = b * PIX + ((y2 / WS) * NW_GRID + (x2 / WS)) * NWIN
               + (y2 % WS) * WS + (x2 % WS);
        bf16* wp = win + (size_t)r * DIM;
#pragma unroll
        for (int j = 0; j < 6; ++j) {
            int c = lane + j * 32;
            wp[c] = __float2bfloat16((v[j] - mu) * rstd * gam[c] + bet[c]);
        }
    }
}

// ---------------------------------------------------------------------------
// K5: x1 = x + window-reverse(proj_out);  h2 = LN2(x1) -> bf16
// ---------------------------------------------------------------------------
__global__ __launch_bounds__(256)
void addln2_kernel(const float* __restrict__ x,
                   const float* __restrict__ po,
                   const float* __restrict__ gam,
                   const float* __restrict__ bet,
                   float* __restrict__ x1,
                   bf16* __restrict__ h2) {
    __shared__ float sm[32][193];
    int p0  = blockIdx.x * 32;
    int b   = p0 / PIX, yx0 = p0 % PIX;
    int tid = threadIdx.x, warp = tid >> 5, lane = tid & 31;

#pragma unroll
    for (int t = 0; t < 4; ++t) {
        int pix = warp * 4 + t;
        int yx = yx0 + pix;
        int y  = yx / HW, xx = yx % HW;
        int y2 = (y  + HW - SHIFTV) % HW;
        int x2 = (xx + HW - SHIFTV) % HW;
        int r  = b * PIX + ((y2 / WS) * NW_GRID + (x2 / WS)) * NWIN
               + (y2 % WS) * WS + (x2 % WS);
        const float* pp = po + (size_t)r * DIM;
#pragma unroll
        for (int j = 0; j < 6; ++j) {
            int c = lane + j * 32;
            sm[pix][c] = pp[c];
        }
    }
    __syncthreads();

    const float* xb = x  + (size_t)b * (DIM * PIX) + yx0;
    float*       xo = x1 + (size_t)b * (DIM * PIX) + yx0;
#pragma unroll
    for (int cc = 0; cc < 24; ++cc) {
        int c = warp + cc * 8;
        float v = xb[(size_t)c * PIX + lane] + sm[lane][c];
        xo[(size_t)c * PIX + lane] = v;
        sm[lane][c] = v;
    }
    __syncthreads();

#pragma unroll
    for (int t = 0; t < 4; ++t) {
        int pix = warp * 4 + t;
        float v[6], s = 0.f, sq = 0.f;
#pragma unroll
        for (int j = 0; j < 6; ++j) {
            float u = sm[pix][lane + j * 32];
            v[j] = u; s += u; sq += u * u;
        }
#pragma unroll
        for (int o = 16; o; o >>= 1) {
            s  += __shfl_xor_sync(0xffffffffu, s,  o);
            sq += __shfl_xor_sync(0xffffffffu, sq, o);
        }
        float mu   = s * (1.f / DIM);
        float var  = sq * (1.f / DIM) - mu * mu;
        float rstd = rsqrtf(var + 1e-5f);

        bf16* hp = h2 + (size_t)(p0 + pix) * DIM;
#pragma unroll
        for (int j = 0; j < 6; ++j) {
            int c = lane + j * 32;
            hp[c] = __float2bfloat16((v[j] - mu) * rstd * gam[c] + bet[c]);
        }
    }
}

// ---------------------------------------------------------------------------
// Launch
// ---------------------------------------------------------------------------
extern "C" void kernel_launch(void* const* d_in, const int* in_sizes, int n_in,
                              void* d_out, int out_size) {
    const float* x      = (const float*)d_in[0];
    const float* n1g    = (const float*)d_in[1];
    const float* n1b    = (const float*)d_in[2];
    const float* qkv_w  = (const float*)d_in[3];
    const float* qkv_b  = (const float*)d_in[4];
    const float* proj_w = (const float*)d_in[5];
    const float* proj_b = (const float*)d_in[6];
    const float* relb   = (const float*)d_in[7];
    const float* n2g    = (const float*)d_in[8];
    const float* n2b    = (const float*)d_in[9];
    const float* fc1_w  = (const float*)d_in[10];
    const float* fc1_b  = (const float*)d_in[11];
    const float* fc2_w  = (const float*)d_in[12];
    const float* fc2_b  = (const float*)d_in[13];
    float* out = (float*)d_out;

    bf16 *ba, *bb, *bg, *wqkv, *wproj, *wfc1, *wfc2, *bmat;
    float *bpo, *bx1;
    cudaGetSymbolAddress((void**)&ba,   gb_a);
    cudaGetSymbolAddress((void**)&bb,   gb_b);
    cudaGetSymbolAddress((void**)&bg,   gb_big);
    cudaGetSymbolAddress((void**)&bpo,  g_projo);
    cudaGetSymbolAddress((void**)&bx1,  g_x1);
    cudaGetSymbolAddress((void**)&wqkv, g_qkv_wt);
    cudaGetSymbolAddress((void**)&wproj,g_proj_wt);
    cudaGetSymbolAddress((void**)&wfc1, g_fc1_wt);
    cudaGetSymbolAddress((void**)&wfc2, g_fc2_wt);
    cudaGetSymbolAddress((void**)&bmat, g_biasmat);

    // 0) weight transposes + bias/mask matrices
    transpose_all<<<432, dim3(32, 8)>>>(qkv_w, proj_w, fc1_w, fc2_w,
                                        wqkv, wproj, wfc1, wfc2);
    bias_build<<<24, 256>>>(relb, bmat);

    // 1) LN1 + roll + window partition -> ba = win[50176,192] bf16
    ln1_win_kernel<<<NPIX / 32, 256>>>(x, n1g, n1b, ba);

    // 2) QKV GEMM -> bg[50176,576] bf16
    mma_gemm<2><<<dim3(576 / BN, NPIX / BM), 256>>>(ba, wqkv, qkv_b, bg,
                                                    nullptr, 576, 192);
    // 3) MMA attention -> bb[50176,192] bf16
    attn_mma_kernel<<<1024 * HEADS, 128>>>(bg, bmat, bb);

    // 4) proj GEMM -> bpo fp32
    mma_gemm<0><<<dim3(192 / BN, NPIX / BM), 256>>>(bb, wproj, proj_b, bpo,
                                                    nullptr, 192, 192);
    // 5) residual + LN2 -> bx1 (NCHW fp32), ba = h2 bf16
    addln2_kernel<<<NPIX / 32, 256>>>(x, bpo, n2g, n2b, bx1, ba);

    // 6) fc1 + GELU -> bg[50176,768] bf16
    mma_gemm<1><<<dim3(768 / BN, NPIX / BM), 256>>>(ba, wfc1, fc1_b, bg,
                                                    nullptr, 768, 192);
    // 7) fc2 + fused residual -> out (NCHW fp32)
    mma_gemm<3><<<dim3(192 / BN, NPIX / BM), 256>>>(bg, wfc2, fc2_b, out,
                                                    bx1, 192, 768);
}

// round 11
// speedup vs baseline: 4.2861x; 1.0206x over previous
#include <cuda_runtime.h>
#include <cuda_bf16.h>
#include <math.h>
#include <stdint.h>

// ---------------------------------------------------------------------------
// Problem constants
// ---------------------------------------------------------------------------
#define BATCH   16
#define DIM     192
#define HW      56
#define PIX     3136            // 56*56
#define NPIX    50176           // 16*3136
#define WS      7
#define SHIFTV  3
#define NWIN    49
#define HEADS   6
#define HD      32
#define NW_GRID 8
#define SCALE_Q 0.1767766952966369f

typedef __nv_bfloat16 bf16;

// ---------------------------------------------------------------------------
// Scratch buffers (allocation-free: device globals)
// ---------------------------------------------------------------------------
__device__ __align__(128) bf16  gb_a   [NPIX * DIM];   // win (ln1 out) / h2 (ln2 out)
__device__ __align__(128) bf16  gb_b   [NPIX * DIM];   // attn out
__device__ __align__(128) bf16  gb_big [NPIX * 768];   // qkv out (576 used) / fc1 out
__device__ __align__(128) float g_projo[NPIX * DIM];   // proj out (fp32)
__device__ __align__(128) float g_x1   [NPIX * DIM];   // residual-1 (NCHW)
// transposed bf16 weights Wt[N][K]
__device__ __align__(128) bf16 g_qkv_wt [576 * 192];
__device__ __align__(128) bf16 g_proj_wt[192 * 192];
__device__ __align__(128) bf16 g_fc1_wt [768 * 192];
__device__ __align__(128) bf16 g_fc2_wt [192 * 768];
// precomputed attention bias+mask matrices: [head*4+cls][64][64] bf16
__device__ __align__(128) bf16 g_biasmat[24 * 64 * 64];

// ---------------------------------------------------------------------------
// PTX helpers
// ---------------------------------------------------------------------------
__device__ __forceinline__ void mma_bf16(float c[4], const uint32_t a[4],
                                         const uint32_t b0, const uint32_t b1) {
    asm volatile(
        "mma.sync.aligned.m16n8k16.row.col.f32.bf16.bf16.f32 "
        "{%0,%1,%2,%3}, {%4,%5,%6,%7}, {%8,%9}, {%0,%1,%2,%3};"
        : "+f"(c[0]), "+f"(c[1]), "+f"(c[2]), "+f"(c[3])
        : "r"(a[0]), "r"(a[1]), "r"(a[2]), "r"(a[3]),
          "r"(b0), "r"(b1));
}
__device__ __forceinline__ void ldsm4(uint32_t r[4], uint32_t addr) {
    asm volatile("ldmatrix.sync.aligned.m8n8.x4.shared.b16 {%0,%1,%2,%3}, [%4];"
                 : "=r"(r[0]), "=r"(r[1]), "=r"(r[2]), "=r"(r[3]) : "r"(addr));
}
__device__ __forceinline__ void ldsm4t(uint32_t r[4], uint32_t addr) {
    asm volatile("ldmatrix.sync.aligned.m8n8.x4.trans.shared.b16 {%0,%1,%2,%3}, [%4];"
                 : "=r"(r[0]), "=r"(r[1]), "=r"(r[2]), "=r"(r[3]) : "r"(addr));
}
__device__ __forceinline__ void cp16(uint32_t dst, const void* src) {
    asm volatile("cp.async.cg.shared.global [%0], [%1], 16;"
                 :: "r"(dst), "l"(src));
}
__device__ __forceinline__ void cp_commit() {
    asm volatile("cp.async.commit_group;" ::: "memory");
}
template <int N>
__device__ __forceinline__ void cp_wait() {
    asm volatile("cp.async.wait_group %0;" :: "n"(N) : "memory");
}
__device__ __forceinline__ uint32_t sptr(const void* p) {
    return (uint32_t)__cvta_generic_to_shared(p);
}
__device__ __forceinline__ float bflo(uint32_t u) {
    return __uint_as_float(u << 16);
}
__device__ __forceinline__ float bfhi(uint32_t u) {
    return __uint_as_float(u & 0xffff0000u);
}
__device__ __forceinline__ uint32_t packbf(float a, float b) {
    __nv_bfloat162 t = __floats2bfloat162_rn(a, b);
    return *(uint32_t*)&t;
}

// ---------------------------------------------------------------------------
// Persistent bf16 tensor-core GEMM: C[NPIX,Ntot] = A[NPIX,K] @ Wt[N,K]^T + bias
// BM=128, BN=96, BKC=32; 256 threads = 8 warps (4M x 2N), warp tile 32x48.
// grid = 2*SMs; each CTA owns a contiguous chunk of tiles (m-fastest).
// BRES=1 (K<=192): full B tile resident in smem as S panels, loaded once
//   per n-index; loop stages only A (continuous 3-buf ring across tiles).
// BRES=0 (fc2):    A and B both staged per k-stage (3-buf rings).
// MODE: 0 = fp32 out, 1 = bf16+GELU out, 2 = bf16 out,
//       3 = fp32 NCHW out with fused residual add (out = x1 + acc+bias).
// ---------------------------------------------------------------------------
#define BM 128
#define BN 96
#define BKC 32
#define MT (NPIX / BM)          // 392 m-tiles (M is always NPIX)
#define SMEMA (3 * BM * 64)     // 24576
#define SMEM_BRES1 (SMEMA + 6 * BN * 64)   // 61440
#define SMEM_BRES0 (SMEMA + 3 * BN * 64)   // 43008

template <int MODE, int BRES>
__global__ __launch_bounds__(256, 2)
void mma_gemm(const bf16* __restrict__ A, const bf16* __restrict__ Bt,
              const float* __restrict__ bias, void* __restrict__ Cout,
              const float* __restrict__ x1aux, int Ntot, int K) {
    extern __shared__ char dsm[];
    const uint32_t aAbase = sptr(dsm);
    const uint32_t aBbase = aAbase + SMEMA;

    int tid = threadIdx.x, lane = tid & 31, wid = tid >> 5;
    int wm = wid & 3, wn = wid >> 2;

    const int S = K / BKC;
    int NT = Ntot / BN;
    int ntiles = MT * NT;
    int L = (ntiles + gridDim.x - 1) / gridDim.x;
    int t0 = blockIdx.x * L;
    int t1 = t0 + L; if (t1 > ntiles) t1 = ntiles;
    if (t0 >= t1) return;

    // ldmatrix per-lane address components (validated pattern)
    uint32_t aRow[2], aSw[2];
    int aHalf = lane >> 4;
#pragma unroll
    for (int tm = 0; tm < 2; ++tm) {
        int r = wm * 32 + tm * 16 + (lane & 15);
        aRow[tm] = r * 64;
        aSw[tm]  = (r >> 1) & 3;
    }
    uint32_t bRow[3], bSw[3];
    int bHalf = (lane >> 3) & 1;
#pragma unroll
    for (int p = 0; p < 3; ++p) {
        int r = wn * 48 + p * 16 + ((lane >> 4) << 3) + (lane & 7);
        bRow[p] = r * 64;
        bSw[p]  = (r >> 1) & 3;
    }

    float acc[2][6][4];
#pragma unroll
    for (int i = 0; i < 2; ++i)
#pragma unroll
        for (int j = 0; j < 6; ++j)
#pragma unroll
            for (int l = 0; l < 4; ++l) acc[i][j][l] = 0.f;

    auto compute = [&](uint32_t bA, uint32_t bB) {
#pragma unroll
        for (int kss = 0; kss < 2; ++kss) {
            uint32_t af[2][4], bq[3][4];
#pragma unroll
            for (int tm = 0; tm < 2; ++tm)
                ldsm4(af[tm], bA + aRow[tm]
                      + ((((kss << 1) | aHalf) ^ aSw[tm]) << 4));
#pragma unroll
            for (int p = 0; p < 3; ++p)
                ldsm4(bq[p], bB + bRow[p]
                      + ((((kss << 1) | bHalf) ^ bSw[p]) << 4));
#pragma unroll
            for (int tm = 0; tm < 2; ++tm)
#pragma unroll
                for (int tn = 0; tn < 6; ++tn)
                    mma_bf16(acc[tm][tn], af[tm],
                             bq[tn >> 1][(tn & 1) << 1],
                             bq[tn >> 1][((tn & 1) << 1) + 1]);
        }
    };

    auto epi = [&](int m0, int n0) {
        int q = lane & 3;
#pragma unroll
        for (int tm = 0; tm < 2; ++tm) {
            int r = m0 + wm * 32 + tm * 16 + (lane >> 2);
            size_t base1 = 0, base2 = 0;
            if (MODE == 3) {
                int b1 = r / PIX, yx1 = r % PIX;
                int r2 = r + 8;
                int b2 = r2 / PIX, yx2 = r2 % PIX;
                base1 = (size_t)b1 * (DIM * PIX) + yx1;
                base2 = (size_t)b2 * (DIM * PIX) + yx2;
            }
#pragma unroll
            for (int tn = 0; tn < 6; ++tn) {
                int cl = wn * 48 + tn * 8 + (q << 1);
                float b0 = __ldg(bias + n0 + cl);
                float b1v = __ldg(bias + n0 + cl + 1);
                float v0 = acc[tm][tn][0] + b0;
                float v1 = acc[tm][tn][1] + b1v;
                float v2 = acc[tm][tn][2] + b0;
                float v3 = acc[tm][tn][3] + b1v;
                if (MODE == 1) {
                    v0 = 0.5f * v0 * (1.f + erff(v0 * 0.70710678118654752f));
                    v1 = 0.5f * v1 * (1.f + erff(v1 * 0.70710678118654752f));
                    v2 = 0.5f * v2 * (1.f + erff(v2 * 0.70710678118654752f));
                    v3 = 0.5f * v3 * (1.f + erff(v3 * 0.70710678118654752f));
                }
                if (MODE == 0) {
                    float* C = (float*)Cout;
                    *(float2*)(C + (size_t)r * Ntot + n0 + cl)       = make_float2(v0, v1);
                    *(float2*)(C + (size_t)(r + 8) * Ntot + n0 + cl) = make_float2(v2, v3);
                } else if (MODE == 3) {
                    float* O = (float*)Cout;
                    size_t o00 = base1 + (size_t)(n0 + cl) * PIX;
                    size_t o01 = base1 + (size_t)(n0 + cl + 1) * PIX;
                    size_t o10 = base2 + (size_t)(n0 + cl) * PIX;
                    size_t o11 = base2 + (size_t)(n0 + cl + 1) * PIX;
                    O[o00] = x1aux[o00] + v0;
                    O[o01] = x1aux[o01] + v1;
                    O[o10] = x1aux[o10] + v2;
                    O[o11] = x1aux[o11] + v3;
                } else {
                    bf16* C = (bf16*)Cout;
                    *(__nv_bfloat162*)(C + (size_t)r * Ntot + n0 + cl) =
                        __floats2bfloat162_rn(v0, v1);
                    *(__nv_bfloat162*)(C + (size_t)(r + 8) * Ntot + n0 + cl) =
                        __floats2bfloat162_rn(v2, v3);
                }
            }
        }
#pragma unroll
        for (int i = 0; i < 2; ++i)
#pragma unroll
            for (int j = 0; j < 6; ++j)
#pragma unroll
                for (int l = 0; l < 4; ++l) acc[i][j][l] = 0.f;
    };

    if (BRES) {
        // ---- B resident: process tiles grouped by n-index ----
        int t = t0;
        while (t < t1) {
            int nIdx = t / MT;
            int tend = (nIdx + 1) * MT; if (tend > t1) tend = t1;
            int n0 = nIdx * BN;
            __syncthreads();               // drain previous group's smem use
            {   // load all S B panels (S*384 16B-groups)
                int total = S * 384;
                for (int e = tid; e < total; e += 256) {
                    int panel = e / 384;
                    int rg = e - panel * 384;
                    int r = rg >> 2, g4 = rg & 3;
                    uint32_t dst = aBbase + panel * (BN * 64) + r * 64
                                 + ((g4 ^ ((r >> 1) & 3)) << 4);
                    cp16(dst, Bt + (size_t)(n0 + r) * K + panel * BKC + g4 * 8);
                }
                cp_commit();
            }
            int G = (tend - t) * S;
            // staging-side counters
            int sm0 = (t % MT) * BM, sks = 0, sbuf = 0;
            auto stageA = [&]() {
                uint32_t dstb = aAbase + sbuf * (BM * 64);
                int kc = sks * BKC;
#pragma unroll
                for (int i = 0; i < 2; ++i) {
                    int e = (i << 8) + tid;
                    int row = e >> 2, g4 = e & 3;
                    cp16(dstb + row * 64 + ((g4 ^ ((row >> 1) & 3)) << 4),
                         A + (size_t)(sm0 + row) * K + kc + g4 * 8);
                }
                cp_commit();
                if (++sks == S) { sks = 0; sm0 += BM; }
                if (++sbuf == 3) sbuf = 0;
            };
            stageA(); stageA();            // prologue: 2 stages in flight
            int cm0 = (t % MT) * BM, cks = 0, cbuf = 0;
            for (int g = 0; g < G; ++g) {
                if (g + 1 < G) cp_wait<1>(); else cp_wait<0>();
                __syncthreads();
                if (g + 2 < G) stageA();
                compute(aAbase + cbuf * (BM * 64), aBbase + cks * (BN * 64));
                if (++cks == S) { cks = 0; epi(cm0, n0); cm0 += BM; }
                if (++cbuf == 3) cbuf = 0;
            }
            t = tend;
        }
    } else {
        // ---- streaming B (fc2): one continuous pipeline over the chunk ----
        int G = (t1 - t0) * S;
        int sm0 = (t0 % MT) * BM, sn0 = (t0 / MT) * BN, sks = 0, sbuf = 0;
        auto stageAB = [&]() {
            uint32_t dA = aAbase + sbuf * (BM * 64);
            uint32_t dB = aBbase + sbuf * (BN * 64);
            int kc = sks * BKC;
#pragma unroll
            for (int i = 0; i < 2; ++i) {
                int e = (i << 8) + tid;
                int row = e >> 2, g4 = e & 3;
                cp16(dA + row * 64 + ((g4 ^ ((row >> 1) & 3)) << 4),
                     A + (size_t)(sm0 + row) * K + kc + g4 * 8);
            }
            {
                int row = tid >> 2, g4 = tid & 3;
                cp16(dB + row * 64 + ((g4 ^ ((row >> 1) & 3)) << 4),
                     Bt + (size_t)(sn0 + row) * K + kc + g4 * 8);
            }
            if (tid < 128) {
                int e = 256 + tid;
                int row = e >> 2, g4 = e & 3;
                cp16(dB + row * 64 + ((g4 ^ ((row >> 1) & 3)) << 4),
                     Bt + (size_t)(sn0 + row) * K + kc + g4 * 8);
            }
            cp_commit();
            if (++sks == S) {
                sks = 0; sm0 += BM;
                if (sm0 == NPIX) { sm0 = 0; sn0 += BN; }
            }
            if (++sbuf == 3) sbuf = 0;
        };
        stageAB(); stageAB();
        int cm0 = (t0 % MT) * BM, cn0 = (t0 / MT) * BN, cks = 0, cbuf = 0;
        for (int g = 0; g < G; ++g) {
            if (g + 1 < G) cp_wait<1>(); else cp_wait<0>();
            __syncthreads();
            if (g + 2 < G) stageAB();
            compute(aAbase + cbuf * (BM * 64), aBbase + cbuf * (BN * 64));
            if (++cks == S) {
                cks = 0; epi(cm0, cn0); cm0 += BM;
                if (cm0 == NPIX) { cm0 = 0; cn0 += BN; }
            }
            if (++cbuf == 3) cbuf = 0;
        }
    }
}

// ---------------------------------------------------------------------------
// Bias matrices: [h*4+cls][q(64)][k(64)] = rel_bias + shift-mask, padded = -1e9
// ---------------------------------------------------------------------------
__global__ void bias_build(const float* __restrict__ rel_bias,
                           bf16* __restrict__ bm) {
    int mat = blockIdx.x;            // 0..23
    int h = mat >> 2, cls = mat & 3;
    for (int e = threadIdx.x; e < 4096; e += 256) {
        int qq = e >> 6, kk = e & 63;
        float v = -1e9f;
        if (qq < NWIN && kk < NWIN) {
            int qi = qq / WS, qj = qq % WS, ki = kk / WS, kj = kk % WS;
            int ryq = (cls & 2) ? ((qi < WS - SHIFTV) ? 1 : 2) : 0;
            int rxq = (cls & 1) ? ((qj < WS - SHIFTV) ? 1 : 2) : 0;
            int ryk = (cls & 2) ? ((ki < WS - SHIFTV) ? 1 : 2) : 0;
            int rxk = (cls & 1) ? ((kj < WS - SHIFTV) ? 1 : 2) : 0;
            if (ryq == ryk && rxq == rxk)
                v = rel_bias[((qi - ki + 6) * 13 + (qj - kj + 6)) * HEADS + h];
        }
        bm[mat * 4096 + e] = __float2bfloat16(v);
    }
}

// ---------------------------------------------------------------------------
// K3: MMA windowed attention (unchanged — passing)
// ---------------------------------------------------------------------------
__global__ __launch_bounds__(128)
void attn_mma_kernel(const bf16* __restrict__ qkv,
                     const bf16* __restrict__ biasmat,
                     bf16* __restrict__ ao) {
    __shared__ __align__(16) bf16 sm[3 * 64 * 32];   // Q,K,V: 64 rows x 64B each

    int blk = blockIdx.x;
    int h = blk % HEADS, w = blk / HEADS;
    int widx = w & 63;
    int wi = widx >> 3, wj = widx & 7;
    int cls = ((wi == 7) ? 2 : 0) + ((wj == 7) ? 1 : 0);
    const bf16* bm = biasmat + (size_t)(h * 4 + cls) * 4096;
    int r0 = w * NWIN;
    int tid = threadIdx.x, lane = tid & 31, wid = tid >> 5;

    uint32_t sb = sptr(sm);

    const uint4 z4 = make_uint4(0, 0, 0, 0);
    for (int e = tid; e < 768; e += 128) {
        int mat = e >> 8;               // 0=Q 1=K 2=V
        int rg  = e & 255;
        int row = rg >> 2, g = rg & 3;
        uint32_t dst = sb + mat * 4096 + row * 64 + ((g ^ ((row >> 1) & 3)) << 4);
        uint4 v = z4;
        if (row < NWIN)
            v = *(const uint4*)(qkv + (size_t)(r0 + row) * 576 + mat * 192
                                + h * HD + g * 8);
        *(uint4*)((char*)sm + (dst - sb)) = v;
    }
    __syncthreads();

    int qbase = wid * 16;
    int rw = lane & 7;

    float sacc[8][4];
#pragma unroll
    for (int n = 0; n < 8; ++n)
#pragma unroll
        for (int l = 0; l < 4; ++l) sacc[n][l] = 0.f;

    int aHalf = lane >> 4;
    int arow = qbase + (lane & 15);
    uint32_t aAddrBase = sb + arow * 64;
    uint32_t aSw = (arow >> 1) & 3;
    int bHalf = (lane >> 3) & 1;

#pragma unroll
    for (int c = 0; c < 2; ++c) {
        uint32_t af[4];
        ldsm4(af, aAddrBase + ((((c << 1) | aHalf) ^ aSw) << 4));
#pragma unroll
        for (int t = 0; t < 4; ++t) {
            int brow = t * 16 + ((lane >> 4) << 3) + rw;
            uint32_t bq[4];
            ldsm4(bq, sb + 4096 + brow * 64
                  + ((((c << 1) | bHalf) ^ ((brow >> 1) & 3)) << 4));
            mma_bf16(sacc[2 * t],     af, bq[0], bq[1]);
            mma_bf16(sacc[2 * t + 1], af, bq[2], bq[3]);
        }
    }

    int rA = qbase + (lane >> 2);
    int rB = rA + 8;
    const bf16* bmA = bm + rA * 64 + ((lane & 3) << 1);
    const bf16* bmB = bm + rB * 64 + ((lane & 3) << 1);

    float mx0 = -1e30f, mx1 = -1e30f;
#pragma unroll
    for (int n = 0; n < 8; ++n) {
        uint32_t bb0 = *(const uint32_t*)(bmA + n * 8);
        uint32_t bb1 = *(const uint32_t*)(bmB + n * 8);
        sacc[n][0] = sacc[n][0] * SCALE_Q + bflo(bb0);
        sacc[n][1] = sacc[n][1] * SCALE_Q + bfhi(bb0);
        sacc[n][2] = sacc[n][2] * SCALE_Q + bflo(bb1);
        sacc[n][3] = sacc[n][3] * SCALE_Q + bfhi(bb1);
        mx0 = fmaxf(mx0, fmaxf(sacc[n][0], sacc[n][1]));
        mx1 = fmaxf(mx1, fmaxf(sacc[n][2], sacc[n][3]));
    }
    mx0 = fmaxf(mx0, __shfl_xor_sync(0xffffffffu, mx0, 1));
    mx0 = fmaxf(mx0, __shfl_xor_sync(0xffffffffu, mx0, 2));
    mx1 = fmaxf(mx1, __shfl_xor_sync(0xffffffffu, mx1, 1));
    mx1 = fmaxf(mx1, __shfl_xor_sync(0xffffffffu, mx1, 2));

    float sum0 = 0.f, sum1 = 0.f;
#pragma unroll
    for (int n = 0; n < 8; ++n) {
        sacc[n][0] = __expf(sacc[n][0] - mx0);
        sacc[n][1] = __expf(sacc[n][1] - mx0);
        sacc[n][2] = __expf(sacc[n][2] - mx1);
        sacc[n][3] = __expf(sacc[n][3] - mx1);
        sum0 += sacc[n][0] + sacc[n][1];
        sum1 += sacc[n][2] + sacc[n][3];
    }
    sum0 += __shfl_xor_sync(0xffffffffu, sum0, 1);
    sum0 += __shfl_xor_sync(0xffffffffu, sum0, 2);
    sum1 += __shfl_xor_sync(0xffffffffu, sum1, 1);
    sum1 += __shfl_xor_sync(0xffffffffu, sum1, 2);
    float inv0 = 1.f / sum0, inv1 = 1.f / sum1;

    uint32_t pA[8], pB[8];
#pragma unroll
    for (int n = 0; n < 8; ++n) {
        pA[n] = packbf(sacc[n][0] * inv0, sacc[n][1] * inv0);
        pB[n] = packbf(sacc[n][2] * inv1, sacc[n][3] * inv1);
    }

    float oacc[4][4];
#pragma unroll
    for (int d = 0; d < 4; ++d)
#pragma unroll
        for (int l = 0; l < 4; ++l) oacc[d][l] = 0.f;

#pragma unroll
    for (int kc = 0; kc < 4; ++kc) {
        uint32_t af[4] = { pA[2 * kc], pB[2 * kc], pA[2 * kc + 1], pB[2 * kc + 1] };
        int vrow = kc * 16 + (((lane >> 3) & 1) << 3) + rw;
        uint32_t vswz = (vrow >> 1) & 3;
        int ghalf = (lane >> 4) & 1;
        uint32_t v01[4], v23[4];
        ldsm4t(v01, sb + 8192 + vrow * 64 + (((0 + ghalf) ^ vswz) << 4));
        ldsm4t(v23, sb + 8192 + vrow * 64 + (((2 + ghalf) ^ vswz) << 4));
        mma_bf16(oacc[0], af, v01[0], v01[1]);
        mma_bf16(oacc[1], af, v01[2], v01[3]);
        mma_bf16(oacc[2], af, v23[0], v23[1]);
        mma_bf16(oacc[3], af, v23[2], v23[3]);
    }

    int colb = h * HD + ((lane & 3) << 1);
    if (rA < NWIN) {
        bf16* op = ao + (size_t)(r0 + rA) * DIM + colb;
#pragma unroll
        for (int d = 0; d < 4; ++d)
            *(uint32_t*)(op + d * 8) = packbf(oacc[d][0], oacc[d][1]);
    }
    if (rB < NWIN) {
        bf16* op = ao + (size_t)(r0 + rB) * DIM + colb;
#pragma unroll
        for (int d = 0; d < 4; ++d)
            *(uint32_t*)(op + d * 8) = packbf(oacc[d][2], oacc[d][3]);
    }
}

// ---------------------------------------------------------------------------
// All 4 weight transposes (+bf16 convert) in ONE launch
// ---------------------------------------------------------------------------
__global__ void transpose_all(const float* __restrict__ w0, const float* __restrict__ w1,
                              const float* __restrict__ w2, const float* __restrict__ w3,
                              bf16* __restrict__ t0, bf16* __restrict__ t1,
                              bf16* __restrict__ t2, bf16* __restrict__ t3) {
    __shared__ float t[32][33];
    int bid = blockIdx.x;
    const float* W; bf16* Wt; int K, N, tn, tk;
    if (bid < 108)      { W = w0; Wt = t0; K = 192; N = 576; tn = bid % 18; tk = bid / 18; }
    else if (bid < 144) { bid -= 108; W = w1; Wt = t1; K = 192; N = 192; tn = bid % 6;  tk = bid / 6; }
    else if (bid < 288) { bid -= 144; W = w2; Wt = t2; K = 192; N = 768; tn = bid % 24; tk = bid / 24; }
    else                { bid -= 288; W = w3; Wt = t3; K = 768; N = 192; tn = bid % 6;  tk = bid / 6; }
    int k0 = tk * 32, n0 = tn * 32;
    int tx = threadIdx.x, ty = threadIdx.y;
#pragma unroll
    for (int i = 0; i < 32; i += 8)
        t[ty + i][tx] = W[(size_t)(k0 + ty + i) * N + n0 + tx];
    __syncthreads();
#pragma unroll
    for (int i = 0; i < 32; i += 8)
        Wt[(size_t)(n0 + ty + i) * K + k0 + tx] = __float2bfloat16(t[tx][ty + i]);
}

// ---------------------------------------------------------------------------
// K1: LayerNorm1 + roll(-3,-3) + window partition -> bf16 win
// ---------------------------------------------------------------------------
__global__ __launch_bounds__(256)
void ln1_win_kernel(const float* __restrict__ x,
                    const float* __restrict__ gam,
                    const float* __restrict__ bet,
                    bf16* __restrict__ win) {
    __shared__ float sm[32][193];
    int p0  = blockIdx.x * 32;
    int b   = p0 / PIX, yx0 = p0 % PIX;
    int tid = threadIdx.x, warp = tid >> 5, lane = tid & 31;

    const float* xb = x + (size_t)b * (DIM * PIX) + yx0;
#pragma unroll
    for (int cc = 0; cc < 24; ++cc) {
        int c = warp + cc * 8;
        sm[lane][c] = xb[(size_t)c * PIX + lane];
    }
    __syncthreads();

#pragma unroll
    for (int t = 0; t < 4; ++t) {
        int pix = warp * 4 + t;
        float v[6], s = 0.f, sq = 0.f;
#pragma unroll
        for (int j = 0; j < 6; ++j) {
            float u = sm[pix][lane + j * 32];
            v[j] = u; s += u; sq += u * u;
        }
#pragma unroll
        for (int o = 16; o; o >>= 1) {
            s  += __shfl_xor_sync(0xffffffffu, s,  o);
            sq += __shfl_xor_sync(0xffffffffu, sq, o);
        }
        float mu   = s * (1.f / DIM);
        float var  = sq * (1.f / DIM) - mu * mu;
        float rstd = rsqrtf(var + 1e-5f);

        int yx = yx0 + pix;
        int y  = yx / HW, xx = yx % HW;
        int y2 = (y  + HW - SHIFTV) % HW;
        int x2 = (xx + HW - SHIFTV) % HW;
        int r  = b * PIX + ((y2 / WS) * NW_GRID + (x2 / WS)) * NWIN
               + (y2 % WS) * WS + (x2 % WS);
        bf16* wp = win + (size_t)r * DIM;
#pragma unroll
        for (int j = 0; j < 6; ++j) {
            int c = lane + j * 32;
            wp[c] = __float2bfloat16((v[j] - mu) * rstd * gam[c] + bet[c]);
        }
    }
}

// ---------------------------------------------------------------------------
// K5: x1 = x + window-reverse(proj_out);  h2 = LN2(x1) -> bf16
// ---------------------------------------------------------------------------
__global__ __launch_bounds__(256)
void addln2_kernel(const float* __restrict__ x,
                   const float* __restrict__ po,
                   const float* __restrict__ gam,
                   const float* __restrict__ bet,
                   float* __restrict__ x1,
                   bf16* __restrict__ h2) {
    __shared__ float sm[32][193];
    int p0  = blockIdx.x * 32;
    int b   = p0 / PIX, yx0 = p0 % PIX;
    int tid = threadIdx.x, warp = tid >> 5, lane = tid & 31;

#pragma unroll
    for (int t = 0; t < 4; ++t) {
        int pix = warp * 4 + t;
        int yx = yx0 + pix;
        int y  = yx / HW, xx = yx % HW;
        int y2 = (y  + HW - SHIFTV) % HW;
        int x2 = (xx + HW - SHIFTV) % HW;
        int r  = b * PIX + ((y2 / WS) * NW_GRID + (x2 / WS)) * NWIN
               + (y2 % WS) * WS + (x2 % WS);
        const float* pp = po + (size_t)r * DIM;
#pragma unroll
        for (int j = 0; j < 6; ++j) {
            int c = lane + j * 32;
            sm[pix][c] = pp[c];
        }
    }
    __syncthreads();

    const float* xb = x  + (size_t)b * (DIM * PIX) + yx0;
    float*       xo = x1 + (size_t)b * (DIM * PIX) + yx0;
#pragma unroll
    for (int cc = 0; cc < 24; ++cc) {
        int c = warp + cc * 8;
        float v = xb[(size_t)c * PIX + lane] + sm[lane][c];
        xo[(size_t)c * PIX + lane] = v;
        sm[lane][c] = v;
    }
    __syncthreads();

#pragma unroll
    for (int t = 0; t < 4; ++t) {
        int pix = warp * 4 + t;
        float v[6], s = 0.f, sq = 0.f;
#pragma unroll
        for (int j = 0; j < 6; ++j) {
            float u = sm[pix][lane + j * 32];
            v[j] = u; s += u; sq += u * u;
        }
#pragma unroll
        for (int o = 16; o; o >>= 1) {
            s  += __shfl_xor_sync(0xffffffffu, s,  o);
            sq += __shfl_xor_sync(0xffffffffu, sq, o);
        }
        float mu   = s * (1.f / DIM);
        float var  = sq * (1.f / DIM) - mu * mu;
        float rstd = rsqrtf(var + 1e-5f);

        bf16* hp = h2 + (size_t)(p0 + pix) * DIM;
#pragma unroll
        for (int j = 0; j < 6; ++j) {
            int c = lane + j * 32;
            hp[c] = __float2bfloat16((v[j] - mu) * rstd * gam[c] + bet[c]);
        }
    }
}

// ---------------------------------------------------------------------------
// Launch
// ---------------------------------------------------------------------------
extern "C" void kernel_launch(void* const* d_in, const int* in_sizes, int n_in,
                              void* d_out, int out_size) {
    const float* x      = (const float*)d_in[0];
    const float* n1g    = (const float*)d_in[1];
    const float* n1b    = (const float*)d_in[2];
    const float* qkv_w  = (const float*)d_in[3];
    const float* qkv_b  = (const float*)d_in[4];
    const float* proj_w = (const float*)d_in[5];
    const float* proj_b = (const float*)d_in[6];
    const float* relb   = (const float*)d_in[7];
    const float* n2g    = (const float*)d_in[8];
    const float* n2b    = (const float*)d_in[9];
    const float* fc1_w  = (const float*)d_in[10];
    const float* fc1_b  = (const float*)d_in[11];
    const float* fc2_w  = (const float*)d_in[12];
    const float* fc2_b  = (const float*)d_in[13];
    float* out = (float*)d_out;

    bf16 *ba, *bb, *bg, *wqkv, *wproj, *wfc1, *wfc2, *bmat;
    float *bpo, *bx1;
    cudaGetSymbolAddress((void**)&ba,   gb_a);
    cudaGetSymbolAddress((void**)&bb,   gb_b);
    cudaGetSymbolAddress((void**)&bg,   gb_big);
    cudaGetSymbolAddress((void**)&bpo,  g_projo);
    cudaGetSymbolAddress((void**)&bx1,  g_x1);
    cudaGetSymbolAddress((void**)&wqkv, g_qkv_wt);
    cudaGetSymbolAddress((void**)&wproj,g_proj_wt);
    cudaGetSymbolAddress((void**)&wfc1, g_fc1_wt);
    cudaGetSymbolAddress((void**)&wfc2, g_fc2_wt);
    cudaGetSymbolAddress((void**)&bmat, g_biasmat);

    cudaFuncSetAttribute(mma_gemm<2,1>, cudaFuncAttributeMaxDynamicSharedMemorySize, SMEM_BRES1);
    cudaFuncSetAttribute(mma_gemm<0,1>, cudaFuncAttributeMaxDynamicSharedMemorySize, SMEM_BRES1);
    cudaFuncSetAttribute(mma_gemm<1,1>, cudaFuncAttributeMaxDynamicSharedMemorySize, SMEM_BRES1);
    cudaFuncSetAttribute(mma_gemm<3,0>, cudaFuncAttributeMaxDynamicSharedMemorySize, SMEM_BRES0);

    int dev = 0, nsm = 148;
    cudaGetDevice(&dev);
    cudaDeviceGetAttribute(&nsm, cudaDevAttrMultiProcessorCount, dev);
    int grid = nsm * 2;

    // 0) weight transposes + bias/mask matrices
    transpose_all<<<432, dim3(32, 8)>>>(qkv_w, proj_w, fc1_w, fc2_w,
                                        wqkv, wproj, wfc1, wfc2);
    bias_build<<<24, 256>>>(relb, bmat);

    // 1) LN1 + roll + window partition -> ba = win[50176,192] bf16
    ln1_win_kernel<<<NPIX / 32, 256>>>(x, n1g, n1b, ba);

    // 2) QKV GEMM -> bg[50176,576] bf16
    mma_gemm<2,1><<<grid, 256, SMEM_BRES1>>>(ba, wqkv, qkv_b, bg,
                                             nullptr, 576, 192);
    // 3) MMA attention -> bb[50176,192] bf16
    attn_mma_kernel<<<1024 * HEADS, 128>>>(bg, bmat, bb);

    // 4) proj GEMM -> bpo fp32
    mma_gemm<0,1><<<grid, 256, SMEM_BRES1>>>(bb, wproj, proj_b, bpo,
                                             nullptr, 192, 192);
    // 5) residual + LN2 -> bx1 (NCHW fp32), ba = h2 bf16
    addln2_kernel<<<NPIX / 32, 256>>>(x, bpo, n2g, n2b, bx1, ba);

    // 6) fc1 + GELU -> bg[50176,768] bf16
    mma_gemm<1,1><<<grid, 256, SMEM_BRES1>>>(ba, wfc1, fc1_b, bg,
                                             nullptr, 768, 192);
    // 7) fc2 + fused residual -> out (NCHW fp32)
    mma_gemm<3,0><<<grid, 256, SMEM_BRES0>>>(bg, wfc2, fc2_b, out,
                                             bx1, 192, 768);
}